// round 1
// baseline (speedup 1.0000x reference)
#include <cuda_runtime.h>
#include <math.h>

// ---------------- Problem constants ----------------
#define BATCH 2
#define SEQ   2048
#define DIM   2048
#define HEADS 16
#define QLR   1536
#define KVLR  512
#define RD    64
#define ND    128
#define VD    128
#define NTOK  (BATCH*SEQ)      // 4096
#define DQK   (ND+RD)          // 192
#define EPSF  1e-6f

// ---------------- Scratch (single device global; no allocations) ----------------
#define O_CQ     ((size_t)0)
#define O_KVRAW  (O_CQ     + (size_t)NTOK*QLR)               // 4096*1536
#define O_CKV    (O_KVRAW  + (size_t)NTOK*(KVLR+RD))         // 4096*576
#define O_QN     (O_CKV    + (size_t)NTOK*KVLR)              // 4096*512
#define O_QR     (O_QN     + (size_t)NTOK*HEADS*ND)          // 4096*2048
#define O_Q      (O_QR     + (size_t)NTOK*HEADS*RD)          // 4096*1024
#define O_KVUP   (O_Q      + (size_t)NTOK*HEADS*DQK)         // 4096*3072
#define O_KT     (O_KVUP   + (size_t)NTOK*HEADS*(ND+VD))     // 4096*4096
#define O_V      (O_KT     + (size_t)BATCH*HEADS*DQK*SEQ)    // 2*16*192*2048
#define O_KROPE  (O_V      + (size_t)NTOK*HEADS*VD)          // 4096*2048
#define O_SCORES (O_KROPE  + (size_t)NTOK*RD)                // 4096*64
#define O_ATTN   (O_SCORES + (size_t)BATCH*HEADS*SEQ*SEQ)    // 32*2048*2048
#define O_TOTAL  (O_ATTN   + (size_t)NTOK*HEADS*VD)

__device__ float g_scratch[O_TOTAL];

// ---------------- Reductions ----------------
__device__ __forceinline__ float warpSum(float v) {
    #pragma unroll
    for (int o = 16; o; o >>= 1) v += __shfl_xor_sync(0xffffffffu, v, o);
    return v;
}
__device__ __forceinline__ float warpMax(float v) {
    #pragma unroll
    for (int o = 16; o; o >>= 1) v = fmaxf(v, __shfl_xor_sync(0xffffffffu, v, o));
    return v;
}

// ---------------- Generic batched tiled SGEMM (NN, row-major) ----------------
// C[m,n] = sum_k A[m,k]*B[k,n].  Batched over z = b*Hdim + h with independent
// base offsets per b and per h for each matrix.
// mode 0: plain.  mode 1: causal score GEMM (skip tiles fully above diagonal).
// mode 2: causal P@V GEMM (K-loop limited to blockRow+BM).
#define GBM 128
#define GBN 128
#define GBK 16

__global__ void __launch_bounds__(256, 2) sgemm_k(
    const float* __restrict__ A, const float* __restrict__ B, float* __restrict__ C,
    int M, int N, int K, int lda, int ldb, int ldc,
    long long aB, long long aH, long long bB, long long bH, long long cB, long long cH,
    int Hdim, int mode)
{
    const int z = blockIdx.z;
    const int bb = z / Hdim, hh = z - bb * Hdim;
    A += (size_t)bb * aB + (size_t)hh * aH;
    B += (size_t)bb * bB + (size_t)hh * bH;
    C += (size_t)bb * cB + (size_t)hh * cH;

    const int blockRow = blockIdx.y * GBM;
    const int blockCol = blockIdx.x * GBN;
    if (mode == 1 && blockCol >= blockRow + GBM) return;   // fully masked tile
    const int Kend = (mode == 2) ? min(K, blockRow + GBM) : K;

    __shared__ float As[GBK][GBM];
    __shared__ float Bs[GBK][GBN];

    const int tid = threadIdx.x;
    const int tr = tid >> 4;     // 0..15
    const int tc = tid & 15;     // 0..15

    float acc[8][8];
    #pragma unroll
    for (int i = 0; i < 8; i++)
        #pragma unroll
        for (int j = 0; j < 8; j++) acc[i][j] = 0.f;

    for (int k0 = 0; k0 < Kend; k0 += GBK) {
        // Load A tile: As[kk][m] = A[blockRow+m][k0+kk]; 512 float4s, 2 per thread
        #pragma unroll
        for (int it = 0; it < 2; it++) {
            int v  = tid + it * 256;
            int m  = v >> 2;             // 0..127
            int kq = (v & 3) << 2;       // 0,4,8,12
            float4 val = make_float4(0.f, 0.f, 0.f, 0.f);
            int gm = blockRow + m, gk = k0 + kq;
            if (gm < M && gk < K)
                val = *(const float4*)(A + (size_t)gm * lda + gk);
            As[kq + 0][m] = val.x; As[kq + 1][m] = val.y;
            As[kq + 2][m] = val.z; As[kq + 3][m] = val.w;
        }
        // Load B tile: Bs[kk][n] = B[k0+kk][blockCol+n]
        #pragma unroll
        for (int it = 0; it < 2; it++) {
            int v  = tid + it * 256;
            int kk = v >> 5;             // 0..15
            int nq = (v & 31) << 2;      // 0..124
            float4 val = make_float4(0.f, 0.f, 0.f, 0.f);
            int gk = k0 + kk, gn = blockCol + nq;
            if (gk < K && gn < N)
                val = *(const float4*)(B + (size_t)gk * ldb + gn);
            *(float4*)&Bs[kk][nq] = val;
        }
        __syncthreads();

        #pragma unroll
        for (int kk = 0; kk < GBK; kk++) {
            float ar[8], br[8];
            #pragma unroll
            for (int i = 0; i < 8; i++) ar[i] = As[kk][tr + i * 16];
            #pragma unroll
            for (int j = 0; j < 8; j++) br[j] = Bs[kk][tc + j * 16];
            #pragma unroll
            for (int i = 0; i < 8; i++)
                #pragma unroll
                for (int j = 0; j < 8; j++)
                    acc[i][j] = fmaf(ar[i], br[j], acc[i][j]);
        }
        __syncthreads();
    }

    #pragma unroll
    for (int i = 0; i < 8; i++) {
        int gm = blockRow + tr + i * 16;
        if (gm >= M) continue;
        #pragma unroll
        for (int j = 0; j < 8; j++) {
            int gn = blockCol + tc + j * 16;
            if (gn < N) C[(size_t)gm * ldc + gn] = acc[i][j];
        }
    }
}

// ---------------- Row RMSNorm (general cols, 256 threads/row) ----------------
__global__ void rmsnorm_k(const float* __restrict__ src, float* __restrict__ dst,
                          const float* __restrict__ w, int cols, int sld, int dld)
{
    const size_t row = blockIdx.x;
    const float* s = src + row * (size_t)sld;
    float* d = dst + row * (size_t)dld;
    float ss = 0.f;
    for (int c = threadIdx.x; c < cols; c += blockDim.x) { float v = s[c]; ss += v * v; }
    __shared__ float red[8];
    __shared__ float sinv;
    ss = warpSum(ss);
    if ((threadIdx.x & 31) == 0) red[threadIdx.x >> 5] = ss;
    __syncthreads();
    if (threadIdx.x == 0) {
        float t = 0.f;
        #pragma unroll
        for (int i = 0; i < 8; i++) t += red[i];
        sinv = rsqrtf(t / cols + EPSF);
    }
    __syncthreads();
    const float inv = sinv;
    for (int c = threadIdx.x; c < cols; c += blockDim.x) d[c] = s[c] * inv * w[c];
}

// ---------------- k_rope precompute: per-token RoPE of kv_raw[:, 512:576] ----------------
__global__ void krope_k(const float* __restrict__ kvraw, const float* __restrict__ fc,
                        const float* __restrict__ fs, float* __restrict__ kr)
{
    const int tok = blockIdx.x, i = threadIdx.x;   // 32 threads
    if (i >= RD / 2) return;
    const int t = tok & (SEQ - 1);
    const float* r = kvraw + (size_t)tok * (KVLR + RD) + KVLR;
    float a = r[2 * i], b = r[2 * i + 1];
    float c = fc[t * (RD / 2) + i], s = fs[t * (RD / 2) + i];
    kr[(size_t)tok * RD + 2 * i]     = a * c - b * s;
    kr[(size_t)tok * RD + 2 * i + 1] = a * s + b * c;
}

// ---------------- Q epilogue: per-head rmsnorm(nope) + rope(rope) -> q[tok,h,192] ----------------
__global__ void q_epi_k(const float* __restrict__ qn, const float* __restrict__ qr,
                        const float* __restrict__ qhw,
                        const float* __restrict__ fc, const float* __restrict__ fs,
                        float* __restrict__ qout)
{
    const int tok = blockIdx.x, h = blockIdx.y, tid = threadIdx.x;  // 128 threads
    const int t = tok & (SEQ - 1);
    const float* src = qn + ((size_t)tok * HEADS + h) * ND;
    float v = src[tid];
    float ss = warpSum(v * v);
    __shared__ float red[4];
    __shared__ float sinv;
    if ((tid & 31) == 0) red[tid >> 5] = ss;
    __syncthreads();
    if (tid == 0) sinv = rsqrtf((red[0] + red[1] + red[2] + red[3]) / ND + EPSF);
    __syncthreads();
    float* dst = qout + ((size_t)tok * HEADS + h) * DQK;
    dst[tid] = v * sinv * qhw[tid];
    if (tid < RD / 2) {
        const float* r = qr + ((size_t)tok * HEADS + h) * RD;
        float a = r[2 * tid], b = r[2 * tid + 1];
        float c = fc[t * (RD / 2) + tid], s = fs[t * (RD / 2) + tid];
        dst[ND + 2 * tid]     = a * c - b * s;
        dst[ND + 2 * tid + 1] = a * s + b * c;
    }
}

// ---------------- KV epilogue: rmsnorm k_nope -> K^T [b,h,d,s]; copy v; append roped k_rope ----------------
__global__ void kv_epi_k(const float* __restrict__ kvup, const float* __restrict__ khw,
                         const float* __restrict__ kr,
                         float* __restrict__ kt, float* __restrict__ vout)
{
    const int tok = blockIdx.x, h = blockIdx.y, tid = threadIdx.x;  // 128 threads
    const int b = tok >> 11;           // tok / SEQ
    const int t = tok & (SEQ - 1);
    const float* src = kvup + ((size_t)tok * HEADS + h) * (ND + VD);
    float v = src[tid];
    float ss = warpSum(v * v);
    __shared__ float red[4];
    __shared__ float sinv;
    if ((tid & 31) == 0) red[tid >> 5] = ss;
    __syncthreads();
    if (tid == 0) sinv = rsqrtf((red[0] + red[1] + red[2] + red[3]) / ND + EPSF);
    __syncthreads();
    float* ktb = kt + (size_t)(b * HEADS + h) * DQK * SEQ;
    ktb[(size_t)tid * SEQ + t] = v * sinv * khw[tid];
    vout[((size_t)tok * HEADS + h) * VD + tid] = src[ND + tid];
    if (tid < RD)
        ktb[(size_t)(ND + tid) * SEQ + t] = kr[(size_t)tok * RD + tid];
}

// ---------------- Fused scale + causal mask + softmax (row in smem) ----------------
__global__ void softmax_k(float* __restrict__ scores, float scale)
{
    const int t = blockIdx.x;
    const int z = blockIdx.y;
    float* row = scores + ((size_t)z * SEQ + t) * SEQ;
    __shared__ float buf[SEQ];
    __shared__ float red[8];
    __shared__ float sstat;
    const int len = t + 1;

    float mx = -1e30f;
    for (int s = threadIdx.x; s < len; s += blockDim.x) {
        float v = row[s] * scale;
        buf[s] = v;
        mx = fmaxf(mx, v);
    }
    mx = warpMax(mx);
    if ((threadIdx.x & 31) == 0) red[threadIdx.x >> 5] = mx;
    __syncthreads();
    if (threadIdx.x == 0) {
        float m = -1e30f;
        #pragma unroll
        for (int i = 0; i < 8; i++) m = fmaxf(m, red[i]);
        sstat = m;
    }
    __syncthreads();
    mx = sstat;

    float sum = 0.f;
    for (int s = threadIdx.x; s < len; s += blockDim.x) {
        float e = __expf(buf[s] - mx);
        buf[s] = e;
        sum += e;
    }
    sum = warpSum(sum);
    __syncthreads();
    if ((threadIdx.x & 31) == 0) red[threadIdx.x >> 5] = sum;
    __syncthreads();
    if (threadIdx.x == 0) {
        float tt = 0.f;
        #pragma unroll
        for (int i = 0; i < 8; i++) tt += red[i];
        sstat = 1.f / tt;
    }
    __syncthreads();
    const float inv = sstat;
    for (int s = threadIdx.x; s < len; s += blockDim.x) row[s] = buf[s] * inv;
    // Zero masked tail up to the 128 boundary (read by the K-limited P@V GEMM)
    const int zend = min(SEQ, (len + 127) & ~127);
    for (int s = len + threadIdx.x; s < zend; s += blockDim.x) row[s] = 0.f;
}

// ---------------- Host driver ----------------
static inline void launch_gemm(const float* A, const float* B, float* C,
                               int M, int N, int K, int lda, int ldb, int ldc,
                               long long aB, long long aH, long long bB, long long bH,
                               long long cB, long long cH, int Hdim, int Z, int mode)
{
    dim3 grid((N + GBN - 1) / GBN, (M + GBM - 1) / GBM, Z);
    sgemm_k<<<grid, 256>>>(A, B, C, M, N, K, lda, ldb, ldc,
                           aB, aH, bB, bH, cB, cH, Hdim, mode);
}

extern "C" void kernel_launch(void* const* d_in, const int* in_sizes, int n_in,
                              void* d_out, int out_size)
{
    const float* x        = (const float*)d_in[0];
    const float* fc       = (const float*)d_in[1];
    const float* fs       = (const float*)d_in[2];
    const float* q_down   = (const float*)d_in[3];
    const float* q_norm   = (const float*)d_in[4];
    const float* q_up_n   = (const float*)d_in[5];
    const float* q_up_r   = (const float*)d_in[6];
    const float* kv_down  = (const float*)d_in[7];
    const float* kv_norm  = (const float*)d_in[8];
    const float* kv_up    = (const float*)d_in[9];
    const float* qhw      = (const float*)d_in[10];
    const float* khw      = (const float*)d_in[11];
    const float* wo       = (const float*)d_in[12];
    float* out            = (float*)d_out;

    float* S = nullptr;
    cudaGetSymbolAddress((void**)&S, g_scratch);

    float* CQ     = S + O_CQ;
    float* KVRAW  = S + O_KVRAW;
    float* CKV    = S + O_CKV;
    float* QN     = S + O_QN;
    float* QR     = S + O_QR;
    float* Q      = S + O_Q;
    float* KVUP   = S + O_KVUP;
    float* KT     = S + O_KT;
    float* V      = S + O_V;
    float* KROPE  = S + O_KROPE;
    float* SCORES = S + O_SCORES;
    float* ATTN   = S + O_ATTN;

    // 1) c_q = rmsnorm(x @ q_down_w)
    launch_gemm(x, q_down, CQ, NTOK, QLR, DIM, DIM, QLR, QLR,
                0, 0, 0, 0, 0, 0, 1, 1, 0);
    rmsnorm_k<<<NTOK, 256>>>(CQ, CQ, q_norm, QLR, QLR, QLR);

    // 2) kv_raw = x @ kv_down_w ; c_kv = rmsnorm(kv_raw[:, :512]) ; k_rope precompute
    launch_gemm(x, kv_down, KVRAW, NTOK, KVLR + RD, DIM, DIM, KVLR + RD, KVLR + RD,
                0, 0, 0, 0, 0, 0, 1, 1, 0);
    rmsnorm_k<<<NTOK, 256>>>(KVRAW, CKV, kv_norm, KVLR, KVLR + RD, KVLR);
    krope_k<<<NTOK, 32>>>(KVRAW, fc, fs, KROPE);

    // 3) q_nope / q_rope projections + epilogue -> Q [tok, h, 192]
    launch_gemm(CQ, q_up_n, QN, NTOK, HEADS * ND, QLR, QLR, HEADS * ND, HEADS * ND,
                0, 0, 0, 0, 0, 0, 1, 1, 0);
    launch_gemm(CQ, q_up_r, QR, NTOK, HEADS * RD, QLR, QLR, HEADS * RD, HEADS * RD,
                0, 0, 0, 0, 0, 0, 1, 1, 0);
    q_epi_k<<<dim3(NTOK, HEADS), 128>>>(QN, QR, qhw, fc, fs, Q);

    // 4) kv up-projection + epilogue -> K^T [b,h,192,s], V [tok,h,128]
    launch_gemm(CKV, kv_up, KVUP, NTOK, HEADS * (ND + VD), KVLR,
                KVLR, HEADS * (ND + VD), HEADS * (ND + VD),
                0, 0, 0, 0, 0, 0, 1, 1, 0);
    kv_epi_k<<<dim3(NTOK, HEADS), 128>>>(KVUP, khw, KROPE, KT, V);

    // 5) scores = Q @ K^T per (b,h)  [causal tiles skipped]
    launch_gemm(Q, KT, SCORES, SEQ, SEQ, DQK,
                HEADS * DQK, SEQ, SEQ,
                (long long)SEQ * HEADS * DQK, DQK,
                (long long)HEADS * DQK * SEQ, (long long)DQK * SEQ,
                (long long)HEADS * SEQ * SEQ, (long long)SEQ * SEQ,
                HEADS, BATCH * HEADS, 1);

    // 6) scale + causal softmax (in place), zero masked tail to 128 boundary
    {
        float scale = 1.0f / sqrtf((float)DQK);
        softmax_k<<<dim3(SEQ, BATCH * HEADS), 256>>>(SCORES, scale);
    }

    // 7) attn_out[b,t,h,128] = P @ V per (b,h)   [K loop limited to causal extent]
    launch_gemm(SCORES, V, ATTN, SEQ, VD, SEQ,
                SEQ, HEADS * VD, HEADS * VD,
                (long long)HEADS * SEQ * SEQ, (long long)SEQ * SEQ,
                (long long)SEQ * HEADS * VD, VD,
                (long long)SEQ * HEADS * VD, VD,
                HEADS, BATCH * HEADS, 2);

    // 8) out = attn_out @ wo_w
    launch_gemm(ATTN, wo, out, NTOK, DIM, HEADS * VD,
                HEADS * VD, DIM, DIM,
                0, 0, 0, 0, 0, 0, 1, 1, 0);
}

// round 2
// speedup vs baseline: 2.4288x; 2.4288x over previous
#include <cuda_runtime.h>
#include <math.h>

// ---------------- Problem constants ----------------
#define BATCH 2
#define SEQ   2048
#define DIM   2048
#define HEADS 16
#define QLR   1536
#define KVLR  512
#define RD    64
#define ND    128
#define VD    128
#define NTOK  (BATCH*SEQ)      // 4096
#define DQK   (ND+RD)          // 192
#define EPSF  1e-6f

// ---------------- Scratch (single device global; no allocations) ----------------
#define O_CQ     ((size_t)0)
#define O_KVRAW  (O_CQ     + (size_t)NTOK*QLR)
#define O_CKV    (O_KVRAW  + (size_t)NTOK*(KVLR+RD))
#define O_QN     (O_CKV    + (size_t)NTOK*KVLR)
#define O_QR     (O_QN     + (size_t)NTOK*HEADS*ND)
#define O_Q      (O_QR     + (size_t)NTOK*HEADS*RD)
#define O_KVUP   (O_Q      + (size_t)NTOK*HEADS*DQK)
#define O_KT     (O_KVUP   + (size_t)NTOK*HEADS*(ND+VD))
#define O_V      (O_KT     + (size_t)BATCH*HEADS*DQK*SEQ)
#define O_KROPE  (O_V      + (size_t)NTOK*HEADS*VD)
#define O_SCORES (O_KROPE  + (size_t)NTOK*RD)
#define O_ATTN   (O_SCORES + (size_t)BATCH*HEADS*SEQ*SEQ)
#define O_TOTAL  (O_ATTN   + (size_t)NTOK*HEADS*VD)

__device__ float g_scratch[O_TOTAL];

// ---------------- Reductions ----------------
__device__ __forceinline__ float warpSum(float v) {
    #pragma unroll
    for (int o = 16; o; o >>= 1) v += __shfl_xor_sync(0xffffffffu, v, o);
    return v;
}
__device__ __forceinline__ float warpMax(float v) {
    #pragma unroll
    for (int o = 16; o; o >>= 1) v = fmaxf(v, __shfl_xor_sync(0xffffffffu, v, o));
    return v;
}

// ---------------- tf32 helpers ----------------
__device__ __forceinline__ unsigned f2tf32(float f) {
    unsigned u;
    asm("cvt.rna.tf32.f32 %0, %1;" : "=r"(u) : "f"(f));
    return u;
}

__device__ __forceinline__ void mma_tf32(
    float& d0, float& d1, float& d2, float& d3,
    unsigned a0, unsigned a1, unsigned a2, unsigned a3,
    unsigned b0, unsigned b1)
{
    asm volatile(
        "mma.sync.aligned.m16n8k8.row.col.f32.tf32.tf32.f32 "
        "{%0,%1,%2,%3}, {%4,%5,%6,%7}, {%8,%9}, {%0,%1,%2,%3};"
        : "+f"(d0), "+f"(d1), "+f"(d2), "+f"(d3)
        : "r"(a0), "r"(a1), "r"(a2), "r"(a3), "r"(b0), "r"(b1));
}

// ---------------- Generic batched tiled TF32 tensor-core GEMM (NN, row-major) ----------------
// mode 0: plain.  mode 1: causal score GEMM (skip tiles fully above diagonal).
// mode 2: causal P@V GEMM (K-loop limited to blockRow+BM).
#define GBM 128
#define GBN 128
#define GBK 32
#define SPAD 8

__global__ void __launch_bounds__(256, 2) tf32gemm_k(
    const float* __restrict__ A, const float* __restrict__ B, float* __restrict__ C,
    int M, int N, int K, int lda, int ldb, int ldc,
    long long aB, long long aH, long long bB, long long bH, long long cB, long long cH,
    int Hdim, int mode)
{
    const int z = blockIdx.z;
    const int bb = z / Hdim, hh = z - bb * Hdim;
    A += (size_t)bb * aB + (size_t)hh * aH;
    B += (size_t)bb * bB + (size_t)hh * bH;
    C += (size_t)bb * cB + (size_t)hh * cH;

    const int blockRow = blockIdx.y * GBM;
    const int blockCol = blockIdx.x * GBN;
    if (mode == 1 && blockCol >= blockRow + GBM) return;   // fully masked tile
    const int Kend = (mode == 2) ? min(K, blockRow + GBM) : K;

    __shared__ unsigned As[GBK][GBM + SPAD];   // tf32 bit patterns, [k][m]
    __shared__ unsigned Bs[GBK][GBN + SPAD];   // tf32 bit patterns, [k][n]

    const int tid  = threadIdx.x;
    const int lane = tid & 31;
    const int warp = tid >> 5;
    const int tig  = lane & 3;      // thread in quad
    const int grp  = lane >> 2;     // quad id 0..7
    const int m_off = (warp >> 2) * 64;   // 2 warp-rows
    const int n_off = (warp & 3) * 32;    // 4 warp-cols

    float acc[4][4][4];
    #pragma unroll
    for (int i = 0; i < 4; i++)
        #pragma unroll
        for (int j = 0; j < 4; j++)
            #pragma unroll
            for (int r = 0; r < 4; r++) acc[i][j][r] = 0.f;

    const int nk = (Kend + GBK - 1) / GBK;
    for (int kb = 0; kb < nk; kb++) {
        const int k0 = kb * GBK;
        __syncthreads();   // previous tile fully consumed

        // ---- Global -> SMEM with tf32 conversion ----
        #pragma unroll
        for (int it = 0; it < 4; it++) {
            int v  = tid + it * 256;          // 0..1023
            int m  = v >> 3;                  // 0..127
            int kq = (v & 7) << 2;            // 0,4,...,28
            float4 val = make_float4(0.f, 0.f, 0.f, 0.f);
            int gm = blockRow + m, gk = k0 + kq;
            if (gm < M && gk < K)
                val = *(const float4*)(A + (size_t)gm * lda + gk);
            As[kq + 0][m] = f2tf32(val.x);
            As[kq + 1][m] = f2tf32(val.y);
            As[kq + 2][m] = f2tf32(val.z);
            As[kq + 3][m] = f2tf32(val.w);
        }
        #pragma unroll
        for (int it = 0; it < 4; it++) {
            int v  = tid + it * 256;
            int kk = v >> 5;                  // 0..31
            int nq = (v & 31) << 2;           // 0..124
            float4 val = make_float4(0.f, 0.f, 0.f, 0.f);
            int gk = k0 + kk, gn = blockCol + nq;
            if (gk < K && gn < N)
                val = *(const float4*)(B + (size_t)gk * ldb + gn);
            Bs[kk][nq + 0] = f2tf32(val.x);
            Bs[kk][nq + 1] = f2tf32(val.y);
            Bs[kk][nq + 2] = f2tf32(val.z);
            Bs[kk][nq + 3] = f2tf32(val.w);
        }
        __syncthreads();

        // ---- Compute: 4 k-steps of 8 ----
        #pragma unroll
        for (int ks = 0; ks < GBK; ks += 8) {
            unsigned af[4][4], bf[4][2];
            #pragma unroll
            for (int mt = 0; mt < 4; mt++) {
                int r0 = m_off + mt * 16 + grp;
                af[mt][0] = As[ks + tig]    [r0];
                af[mt][1] = As[ks + tig]    [r0 + 8];
                af[mt][2] = As[ks + tig + 4][r0];
                af[mt][3] = As[ks + tig + 4][r0 + 8];
            }
            #pragma unroll
            for (int nt = 0; nt < 4; nt++) {
                int c0 = n_off + nt * 8 + grp;
                bf[nt][0] = Bs[ks + tig]    [c0];
                bf[nt][1] = Bs[ks + tig + 4][c0];
            }
            #pragma unroll
            for (int mt = 0; mt < 4; mt++)
                #pragma unroll
                for (int nt = 0; nt < 4; nt++)
                    mma_tf32(acc[mt][nt][0], acc[mt][nt][1], acc[mt][nt][2], acc[mt][nt][3],
                             af[mt][0], af[mt][1], af[mt][2], af[mt][3],
                             bf[nt][0], bf[nt][1]);
        }
    }

    // ---- Epilogue ----
    #pragma unroll
    for (int mt = 0; mt < 4; mt++) {
        int r0 = blockRow + m_off + mt * 16 + grp;
        #pragma unroll
        for (int nt = 0; nt < 4; nt++) {
            int c0 = blockCol + n_off + nt * 8 + tig * 2;
            if (c0 < N) {   // N always even; c0 even -> pair in bounds together
                if (r0 < M)
                    *(float2*)(C + (size_t)r0 * ldc + c0) =
                        make_float2(acc[mt][nt][0], acc[mt][nt][1]);
                if (r0 + 8 < M)
                    *(float2*)(C + (size_t)(r0 + 8) * ldc + c0) =
                        make_float2(acc[mt][nt][2], acc[mt][nt][3]);
            }
        }
    }
}

// ---------------- Row RMSNorm (general cols, 256 threads/row) ----------------
__global__ void rmsnorm_k(const float* __restrict__ src, float* __restrict__ dst,
                          const float* __restrict__ w, int cols, int sld, int dld)
{
    const size_t row = blockIdx.x;
    const float* s = src + row * (size_t)sld;
    float* d = dst + row * (size_t)dld;
    float ss = 0.f;
    for (int c = threadIdx.x; c < cols; c += blockDim.x) { float v = s[c]; ss += v * v; }
    __shared__ float red[8];
    __shared__ float sinv;
    ss = warpSum(ss);
    if ((threadIdx.x & 31) == 0) red[threadIdx.x >> 5] = ss;
    __syncthreads();
    if (threadIdx.x == 0) {
        float t = 0.f;
        #pragma unroll
        for (int i = 0; i < 8; i++) t += red[i];
        sinv = rsqrtf(t / cols + EPSF);
    }
    __syncthreads();
    const float inv = sinv;
    for (int c = threadIdx.x; c < cols; c += blockDim.x) d[c] = s[c] * inv * w[c];
}

// ---------------- k_rope precompute ----------------
__global__ void krope_k(const float* __restrict__ kvraw, const float* __restrict__ fc,
                        const float* __restrict__ fs, float* __restrict__ kr)
{
    const int tok = blockIdx.x, i = threadIdx.x;   // 32 threads
    if (i >= RD / 2) return;
    const int t = tok & (SEQ - 1);
    const float* r = kvraw + (size_t)tok * (KVLR + RD) + KVLR;
    float a = r[2 * i], b = r[2 * i + 1];
    float c = fc[t * (RD / 2) + i], s = fs[t * (RD / 2) + i];
    kr[(size_t)tok * RD + 2 * i]     = a * c - b * s;
    kr[(size_t)tok * RD + 2 * i + 1] = a * s + b * c;
}

// ---------------- Q epilogue ----------------
__global__ void q_epi_k(const float* __restrict__ qn, const float* __restrict__ qr,
                        const float* __restrict__ qhw,
                        const float* __restrict__ fc, const float* __restrict__ fs,
                        float* __restrict__ qout)
{
    const int tok = blockIdx.x, h = blockIdx.y, tid = threadIdx.x;  // 128 threads
    const int t = tok & (SEQ - 1);
    const float* src = qn + ((size_t)tok * HEADS + h) * ND;
    float v = src[tid];
    float ss = warpSum(v * v);
    __shared__ float red[4];
    __shared__ float sinv;
    if ((tid & 31) == 0) red[tid >> 5] = ss;
    __syncthreads();
    if (tid == 0) sinv = rsqrtf((red[0] + red[1] + red[2] + red[3]) / ND + EPSF);
    __syncthreads();
    float* dst = qout + ((size_t)tok * HEADS + h) * DQK;
    dst[tid] = v * sinv * qhw[tid];
    if (tid < RD / 2) {
        const float* r = qr + ((size_t)tok * HEADS + h) * RD;
        float a = r[2 * tid], b = r[2 * tid + 1];
        float c = fc[t * (RD / 2) + tid], s = fs[t * (RD / 2) + tid];
        dst[ND + 2 * tid]     = a * c - b * s;
        dst[ND + 2 * tid + 1] = a * s + b * c;
    }
}

// ---------------- KV epilogue ----------------
__global__ void kv_epi_k(const float* __restrict__ kvup, const float* __restrict__ khw,
                         const float* __restrict__ kr,
                         float* __restrict__ kt, float* __restrict__ vout)
{
    const int tok = blockIdx.x, h = blockIdx.y, tid = threadIdx.x;  // 128 threads
    const int b = tok >> 11;
    const int t = tok & (SEQ - 1);
    const float* src = kvup + ((size_t)tok * HEADS + h) * (ND + VD);
    float v = src[tid];
    float ss = warpSum(v * v);
    __shared__ float red[4];
    __shared__ float sinv;
    if ((tid & 31) == 0) red[tid >> 5] = ss;
    __syncthreads();
    if (tid == 0) sinv = rsqrtf((red[0] + red[1] + red[2] + red[3]) / ND + EPSF);
    __syncthreads();
    float* ktb = kt + (size_t)(b * HEADS + h) * DQK * SEQ;
    ktb[(size_t)tid * SEQ + t] = v * sinv * khw[tid];
    vout[((size_t)tok * HEADS + h) * VD + tid] = src[ND + tid];
    if (tid < RD)
        ktb[(size_t)(ND + tid) * SEQ + t] = kr[(size_t)tok * RD + tid];
}

// ---------------- Fused scale + causal mask + softmax ----------------
__global__ void softmax_k(float* __restrict__ scores, float scale)
{
    const int t = blockIdx.x;
    const int z = blockIdx.y;
    float* row = scores + ((size_t)z * SEQ + t) * SEQ;
    __shared__ float buf[SEQ];
    __shared__ float red[8];
    __shared__ float sstat;
    const int len = t + 1;

    float mx = -1e30f;
    for (int s = threadIdx.x; s < len; s += blockDim.x) {
        float v = row[s] * scale;
        buf[s] = v;
        mx = fmaxf(mx, v);
    }
    mx = warpMax(mx);
    if ((threadIdx.x & 31) == 0) red[threadIdx.x >> 5] = mx;
    __syncthreads();
    if (threadIdx.x == 0) {
        float m = -1e30f;
        #pragma unroll
        for (int i = 0; i < 8; i++) m = fmaxf(m, red[i]);
        sstat = m;
    }
    __syncthreads();
    mx = sstat;

    float sum = 0.f;
    for (int s = threadIdx.x; s < len; s += blockDim.x) {
        float e = __expf(buf[s] - mx);
        buf[s] = e;
        sum += e;
    }
    sum = warpSum(sum);
    __syncthreads();
    if ((threadIdx.x & 31) == 0) red[threadIdx.x >> 5] = sum;
    __syncthreads();
    if (threadIdx.x == 0) {
        float tt = 0.f;
        #pragma unroll
        for (int i = 0; i < 8; i++) tt += red[i];
        sstat = 1.f / tt;
    }
    __syncthreads();
    const float inv = sstat;
    for (int s = threadIdx.x; s < len; s += blockDim.x) row[s] = buf[s] * inv;
    const int zend = min(SEQ, (len + 127) & ~127);
    for (int s = len + threadIdx.x; s < zend; s += blockDim.x) row[s] = 0.f;
}

// ---------------- Host driver ----------------
static inline void launch_gemm(const float* A, const float* B, float* C,
                               int M, int N, int K, int lda, int ldb, int ldc,
                               long long aB, long long aH, long long bB, long long bH,
                               long long cB, long long cH, int Hdim, int Z, int mode)
{
    dim3 grid((N + GBN - 1) / GBN, (M + GBM - 1) / GBM, Z);
    tf32gemm_k<<<grid, 256>>>(A, B, C, M, N, K, lda, ldb, ldc,
                              aB, aH, bB, bH, cB, cH, Hdim, mode);
}

extern "C" void kernel_launch(void* const* d_in, const int* in_sizes, int n_in,
                              void* d_out, int out_size)
{
    const float* x        = (const float*)d_in[0];
    const float* fc       = (const float*)d_in[1];
    const float* fs       = (const float*)d_in[2];
    const float* q_down   = (const float*)d_in[3];
    const float* q_norm   = (const float*)d_in[4];
    const float* q_up_n   = (const float*)d_in[5];
    const float* q_up_r   = (const float*)d_in[6];
    const float* kv_down  = (const float*)d_in[7];
    const float* kv_norm  = (const float*)d_in[8];
    const float* kv_up    = (const float*)d_in[9];
    const float* qhw      = (const float*)d_in[10];
    const float* khw      = (const float*)d_in[11];
    const float* wo       = (const float*)d_in[12];
    float* out            = (float*)d_out;

    float* S = nullptr;
    cudaGetSymbolAddress((void**)&S, g_scratch);

    float* CQ     = S + O_CQ;
    float* KVRAW  = S + O_KVRAW;
    float* CKV    = S + O_CKV;
    float* QN     = S + O_QN;
    float* QR     = S + O_QR;
    float* Q      = S + O_Q;
    float* KVUP   = S + O_KVUP;
    float* KT     = S + O_KT;
    float* V      = S + O_V;
    float* KROPE  = S + O_KROPE;
    float* SCORES = S + O_SCORES;
    float* ATTN   = S + O_ATTN;

    // 1) c_q = rmsnorm(x @ q_down_w)
    launch_gemm(x, q_down, CQ, NTOK, QLR, DIM, DIM, QLR, QLR,
                0, 0, 0, 0, 0, 0, 1, 1, 0);
    rmsnorm_k<<<NTOK, 256>>>(CQ, CQ, q_norm, QLR, QLR, QLR);

    // 2) kv_raw = x @ kv_down_w ; c_kv = rmsnorm(kv_raw[:, :512]) ; k_rope
    launch_gemm(x, kv_down, KVRAW, NTOK, KVLR + RD, DIM, DIM, KVLR + RD, KVLR + RD,
                0, 0, 0, 0, 0, 0, 1, 1, 0);
    rmsnorm_k<<<NTOK, 256>>>(KVRAW, CKV, kv_norm, KVLR, KVLR + RD, KVLR);
    krope_k<<<NTOK, 32>>>(KVRAW, fc, fs, KROPE);

    // 3) q_nope / q_rope projections + epilogue -> Q [tok, h, 192]
    launch_gemm(CQ, q_up_n, QN, NTOK, HEADS * ND, QLR, QLR, HEADS * ND, HEADS * ND,
                0, 0, 0, 0, 0, 0, 1, 1, 0);
    launch_gemm(CQ, q_up_r, QR, NTOK, HEADS * RD, QLR, QLR, HEADS * RD, HEADS * RD,
                0, 0, 0, 0, 0, 0, 1, 1, 0);
    q_epi_k<<<dim3(NTOK, HEADS), 128>>>(QN, QR, qhw, fc, fs, Q);

    // 4) kv up-projection + epilogue -> K^T [b,h,192,s], V [tok,h,128]
    launch_gemm(CKV, kv_up, KVUP, NTOK, HEADS * (ND + VD), KVLR,
                KVLR, HEADS * (ND + VD), HEADS * (ND + VD),
                0, 0, 0, 0, 0, 0, 1, 1, 0);
    kv_epi_k<<<dim3(NTOK, HEADS), 128>>>(KVUP, khw, KROPE, KT, V);

    // 5) scores = Q @ K^T per (b,h)  [causal tiles skipped]
    launch_gemm(Q, KT, SCORES, SEQ, SEQ, DQK,
                HEADS * DQK, SEQ, SEQ,
                (long long)SEQ * HEADS * DQK, DQK,
                (long long)HEADS * DQK * SEQ, (long long)DQK * SEQ,
                (long long)HEADS * SEQ * SEQ, (long long)SEQ * SEQ,
                HEADS, BATCH * HEADS, 1);

    // 6) scale + causal softmax (in place), zero masked tail to 128 boundary
    {
        float scale = 1.0f / sqrtf((float)DQK);
        softmax_k<<<dim3(SEQ, BATCH * HEADS), 256>>>(SCORES, scale);
    }

    // 7) attn_out[b,t,h,128] = P @ V per (b,h)   [K limited to causal extent]
    launch_gemm(SCORES, V, ATTN, SEQ, VD, SEQ,
                SEQ, HEADS * VD, HEADS * VD,
                (long long)HEADS * SEQ * SEQ, (long long)SEQ * SEQ,
                (long long)SEQ * HEADS * VD, VD,
                (long long)SEQ * HEADS * VD, VD,
                HEADS, BATCH * HEADS, 2);

    // 8) out = attn_out @ wo_w
    launch_gemm(ATTN, wo, out, NTOK, DIM, HEADS * VD,
                HEADS * VD, DIM, DIM,
                0, 0, 0, 0, 0, 0, 1, 1, 0);
}

// round 3
// speedup vs baseline: 3.3161x; 1.3653x over previous
#include <cuda_runtime.h>
#include <math.h>

// ---------------- Problem constants ----------------
#define BATCH 2
#define SEQ   2048
#define DIM   2048
#define HEADS 16
#define QLR   1536
#define KVLR  512
#define RD    64
#define ND    128
#define VD    128
#define NTOK  (BATCH*SEQ)      // 4096
#define DQK   (ND+RD)          // 192
#define EPSF  1e-6f

// ---------------- Scratch (single device global; no allocations) ----------------
#define O_CQ     ((size_t)0)
#define O_KVRAW  (O_CQ     + (size_t)NTOK*QLR)
#define O_CKV    (O_KVRAW  + (size_t)NTOK*(KVLR+RD))
#define O_QN     (O_CKV    + (size_t)NTOK*KVLR)
#define O_QR     (O_QN     + (size_t)NTOK*HEADS*ND)
#define O_Q      (O_QR     + (size_t)NTOK*HEADS*RD)
#define O_KVUP   (O_Q      + (size_t)NTOK*HEADS*DQK)
#define O_KT     (O_KVUP   + (size_t)NTOK*HEADS*(ND+VD))
#define O_V      (O_KT     + (size_t)BATCH*HEADS*DQK*SEQ)
#define O_KROPE  (O_V      + (size_t)NTOK*HEADS*VD)
#define O_SCORES (O_KROPE  + (size_t)NTOK*RD)
#define O_ATTN   (O_SCORES + (size_t)BATCH*HEADS*SEQ*SEQ)
#define O_TOTAL  (O_ATTN   + (size_t)NTOK*HEADS*VD)

__device__ float g_scratch[O_TOTAL];

// ---------------- Reductions ----------------
__device__ __forceinline__ float warpSum(float v) {
    #pragma unroll
    for (int o = 16; o; o >>= 1) v += __shfl_xor_sync(0xffffffffu, v, o);
    return v;
}
__device__ __forceinline__ float warpMax(float v) {
    #pragma unroll
    for (int o = 16; o; o >>= 1) v = fmaxf(v, __shfl_xor_sync(0xffffffffu, v, o));
    return v;
}

// ---------------- tf32 helpers ----------------
__device__ __forceinline__ unsigned f2tf32(float f) {
    unsigned u;
    asm("cvt.rna.tf32.f32 %0, %1;" : "=r"(u) : "f"(f));
    return u;
}

__device__ __forceinline__ void mma_tf32(
    float& d0, float& d1, float& d2, float& d3,
    unsigned a0, unsigned a1, unsigned a2, unsigned a3,
    unsigned b0, unsigned b1)
{
    asm volatile(
        "mma.sync.aligned.m16n8k8.row.col.f32.tf32.tf32.f32 "
        "{%0,%1,%2,%3}, {%4,%5,%6,%7}, {%8,%9}, {%0,%1,%2,%3};"
        : "+f"(d0), "+f"(d1), "+f"(d2), "+f"(d3)
        : "r"(a0), "r"(a1), "r"(a2), "r"(a3), "r"(b0), "r"(b1));
}

// 16-byte async copy, zero-filled when pred is false
__device__ __forceinline__ void cpasync16(float* smem_dst, const float* gsrc, bool pred) {
    unsigned saddr = (unsigned)__cvta_generic_to_shared(smem_dst);
    int bytes = pred ? 16 : 0;
    asm volatile("cp.async.cg.shared.global [%0], [%1], 16, %2;\n"
                 :: "r"(saddr), "l"(gsrc), "r"(bytes));
}

// ---------------- Batched TF32 GEMM, 2-stage cp.async pipeline ----------------
// C[m,n] = sum_k A[m,k]*B[k,n], row-major NN.  z = b*Hdim + h batching.
// mode 0: plain. mode 1: causal score GEMM (skip tiles above diagonal).
// mode 2: causal P@V GEMM (K limited to blockRow+GBM).
#define GBM 128
#define GBN 128
#define GBK 32
#define APAD 4                  // A row stride 36 -> banks 4*grp+tig (conflict-free)
#define BPAD 8                  // B row stride 136 -> banks 8*tig+grp (conflict-free)
#define A_ST ((GBK) + (APAD))   // 36
#define B_ST ((GBN) + (BPAD))   // 136
#define SMEM_GEMM_BYTES ((2*GBM*A_ST + 2*GBK*B_ST) * 4)   // 71680

__global__ void __launch_bounds__(256, 2) tf32gemm_k(
    const float* __restrict__ A, const float* __restrict__ B, float* __restrict__ C,
    int M, int N, int K, int lda, int ldb, int ldc,
    long long aB, long long aH, long long bB, long long bH, long long cB, long long cH,
    int Hdim, int mode)
{
    extern __shared__ float dynsmem[];
    float* As = dynsmem;                       // [2][GBM][A_ST]
    float* Bs = dynsmem + 2 * GBM * A_ST;      // [2][GBK][B_ST]

    const int z = blockIdx.z;
    const int bb = z / Hdim, hh = z - bb * Hdim;
    A += (size_t)bb * aB + (size_t)hh * aH;
    B += (size_t)bb * bB + (size_t)hh * bH;
    C += (size_t)bb * cB + (size_t)hh * cH;

    const int blockRow = blockIdx.y * GBM;
    const int blockCol = blockIdx.x * GBN;
    if (mode == 1 && blockCol >= blockRow + GBM) return;   // fully masked tile
    const int Kend = (mode == 2) ? min(K, blockRow + GBM) : K;

    const int tid  = threadIdx.x;
    const int lane = tid & 31;
    const int warp = tid >> 5;
    const int tig  = lane & 3;      // thread in quad
    const int grp  = lane >> 2;     // quad id 0..7
    const int m_off = (warp >> 2) * 64;   // 2 warp-rows
    const int n_off = (warp & 3) * 32;    // 4 warp-cols

    // Per-thread chunk coordinates (4 x 16B for A, 4 x 16B for B)
    int am[4], ak[4], bk[4], bn[4];
    #pragma unroll
    for (int it = 0; it < 4; it++) {
        int v = tid + it * 256;
        am[it] = v >> 3;            // 0..127
        ak[it] = (v & 7) << 2;      // 0,4,...,28
        bk[it] = v >> 5;            // 0..31
        bn[it] = (v & 31) << 2;     // 0..124
    }

    // Issue one tile's worth of cp.async into stage st
    auto load_tile = [&](int st, int k0) {
        float* Asb = As + st * GBM * A_ST;
        float* Bsb = Bs + st * GBK * B_ST;
        #pragma unroll
        for (int it = 0; it < 4; it++) {
            int gm = blockRow + am[it], gk = k0 + ak[it];
            bool p = (gm < M) && (gk < K);
            const float* src = p ? (A + (size_t)gm * lda + gk) : A;
            cpasync16(Asb + am[it] * A_ST + ak[it], src, p);
        }
        #pragma unroll
        for (int it = 0; it < 4; it++) {
            int gk = k0 + bk[it], gn = blockCol + bn[it];
            bool p = (gk < K) && (gn < N);
            const float* src = p ? (B + (size_t)gk * ldb + gn) : B;
            cpasync16(Bsb + bk[it] * B_ST + bn[it], src, p);
        }
    };

    float acc[4][4][4];
    #pragma unroll
    for (int i = 0; i < 4; i++)
        #pragma unroll
        for (int j = 0; j < 4; j++)
            #pragma unroll
            for (int r = 0; r < 4; r++) acc[i][j][r] = 0.f;

    const int nk = (Kend + GBK - 1) / GBK;

    load_tile(0, 0);
    asm volatile("cp.async.commit_group;\n" ::);

    for (int kb = 0; kb < nk; kb++) {
        if (kb + 1 < nk) {
            load_tile((kb + 1) & 1, (kb + 1) * GBK);
            asm volatile("cp.async.commit_group;\n" ::);
            asm volatile("cp.async.wait_group 1;\n" ::);
        } else {
            asm volatile("cp.async.wait_group 0;\n" ::);
        }
        __syncthreads();

        const float* Asb = As + (kb & 1) * GBM * A_ST;
        const float* Bsb = Bs + (kb & 1) * GBK * B_ST;

        #pragma unroll
        for (int ks = 0; ks < GBK; ks += 8) {
            unsigned af[4][4], bf[4][2];
            #pragma unroll
            for (int mt = 0; mt < 4; mt++) {
                int r0 = m_off + mt * 16 + grp;
                af[mt][0] = f2tf32(Asb[ r0      * A_ST + ks + tig    ]);
                af[mt][1] = f2tf32(Asb[(r0 + 8) * A_ST + ks + tig    ]);
                af[mt][2] = f2tf32(Asb[ r0      * A_ST + ks + tig + 4]);
                af[mt][3] = f2tf32(Asb[(r0 + 8) * A_ST + ks + tig + 4]);
            }
            #pragma unroll
            for (int nt = 0; nt < 4; nt++) {
                int c0 = n_off + nt * 8 + grp;
                bf[nt][0] = f2tf32(Bsb[(ks + tig    ) * B_ST + c0]);
                bf[nt][1] = f2tf32(Bsb[(ks + tig + 4) * B_ST + c0]);
            }
            #pragma unroll
            for (int mt = 0; mt < 4; mt++)
                #pragma unroll
                for (int nt = 0; nt < 4; nt++)
                    mma_tf32(acc[mt][nt][0], acc[mt][nt][1], acc[mt][nt][2], acc[mt][nt][3],
                             af[mt][0], af[mt][1], af[mt][2], af[mt][3],
                             bf[nt][0], bf[nt][1]);
        }
        __syncthreads();   // stage consumed; safe for next-next prefetch
    }

    // ---- Epilogue ----
    #pragma unroll
    for (int mt = 0; mt < 4; mt++) {
        int r0 = blockRow + m_off + mt * 16 + grp;
        #pragma unroll
        for (int nt = 0; nt < 4; nt++) {
            int c0 = blockCol + n_off + nt * 8 + tig * 2;
            if (c0 < N) {
                if (r0 < M)
                    *(float2*)(C + (size_t)r0 * ldc + c0) =
                        make_float2(acc[mt][nt][0], acc[mt][nt][1]);
                if (r0 + 8 < M)
                    *(float2*)(C + (size_t)(r0 + 8) * ldc + c0) =
                        make_float2(acc[mt][nt][2], acc[mt][nt][3]);
            }
        }
    }
}

// ---------------- Row RMSNorm ----------------
__global__ void rmsnorm_k(const float* __restrict__ src, float* __restrict__ dst,
                          const float* __restrict__ w, int cols, int sld, int dld)
{
    const size_t row = blockIdx.x;
    const float* s = src + row * (size_t)sld;
    float* d = dst + row * (size_t)dld;
    float ss = 0.f;
    for (int c = threadIdx.x; c < cols; c += blockDim.x) { float v = s[c]; ss += v * v; }
    __shared__ float red[8];
    __shared__ float sinv;
    ss = warpSum(ss);
    if ((threadIdx.x & 31) == 0) red[threadIdx.x >> 5] = ss;
    __syncthreads();
    if (threadIdx.x == 0) {
        float t = 0.f;
        #pragma unroll
        for (int i = 0; i < 8; i++) t += red[i];
        sinv = rsqrtf(t / cols + EPSF);
    }
    __syncthreads();
    const float inv = sinv;
    for (int c = threadIdx.x; c < cols; c += blockDim.x) d[c] = s[c] * inv * w[c];
}

// ---------------- k_rope precompute ----------------
__global__ void krope_k(const float* __restrict__ kvraw, const float* __restrict__ fc,
                        const float* __restrict__ fs, float* __restrict__ kr)
{
    const int tok = blockIdx.x, i = threadIdx.x;   // 32 threads
    if (i >= RD / 2) return;
    const int t = tok & (SEQ - 1);
    const float* r = kvraw + (size_t)tok * (KVLR + RD) + KVLR;
    float a = r[2 * i], b = r[2 * i + 1];
    float c = fc[t * (RD / 2) + i], s = fs[t * (RD / 2) + i];
    kr[(size_t)tok * RD + 2 * i]     = a * c - b * s;
    kr[(size_t)tok * RD + 2 * i + 1] = a * s + b * c;
}

// ---------------- Q epilogue ----------------
__global__ void q_epi_k(const float* __restrict__ qn, const float* __restrict__ qr,
                        const float* __restrict__ qhw,
                        const float* __restrict__ fc, const float* __restrict__ fs,
                        float* __restrict__ qout)
{
    const int tok = blockIdx.x, h = blockIdx.y, tid = threadIdx.x;  // 128 threads
    const int t = tok & (SEQ - 1);
    const float* src = qn + ((size_t)tok * HEADS + h) * ND;
    float v = src[tid];
    float ss = warpSum(v * v);
    __shared__ float red[4];
    __shared__ float sinv;
    if ((tid & 31) == 0) red[tid >> 5] = ss;
    __syncthreads();
    if (tid == 0) sinv = rsqrtf((red[0] + red[1] + red[2] + red[3]) / ND + EPSF);
    __syncthreads();
    float* dst = qout + ((size_t)tok * HEADS + h) * DQK;
    dst[tid] = v * sinv * qhw[tid];
    if (tid < RD / 2) {
        const float* r = qr + ((size_t)tok * HEADS + h) * RD;
        float a = r[2 * tid], b = r[2 * tid + 1];
        float c = fc[t * (RD / 2) + tid], s = fs[t * (RD / 2) + tid];
        dst[ND + 2 * tid]     = a * c - b * s;
        dst[ND + 2 * tid + 1] = a * s + b * c;
    }
}

// ---------------- KV epilogue ----------------
__global__ void kv_epi_k(const float* __restrict__ kvup, const float* __restrict__ khw,
                         const float* __restrict__ kr,
                         float* __restrict__ kt, float* __restrict__ vout)
{
    const int tok = blockIdx.x, h = blockIdx.y, tid = threadIdx.x;  // 128 threads
    const int b = tok >> 11;
    const int t = tok & (SEQ - 1);
    const float* src = kvup + ((size_t)tok * HEADS + h) * (ND + VD);
    float v = src[tid];
    float ss = warpSum(v * v);
    __shared__ float red[4];
    __shared__ float sinv;
    if ((tid & 31) == 0) red[tid >> 5] = ss;
    __syncthreads();
    if (tid == 0) sinv = rsqrtf((red[0] + red[1] + red[2] + red[3]) / ND + EPSF);
    __syncthreads();
    float* ktb = kt + (size_t)(b * HEADS + h) * DQK * SEQ;
    ktb[(size_t)tid * SEQ + t] = v * sinv * khw[tid];
    vout[((size_t)tok * HEADS + h) * VD + tid] = src[ND + tid];
    if (tid < RD)
        ktb[(size_t)(ND + tid) * SEQ + t] = kr[(size_t)tok * RD + tid];
}

// ---------------- Fused scale + causal mask + softmax ----------------
__global__ void softmax_k(float* __restrict__ scores, float scale)
{
    const int t = blockIdx.x;
    const int z = blockIdx.y;
    float* row = scores + ((size_t)z * SEQ + t) * SEQ;
    __shared__ float buf[SEQ];
    __shared__ float red[8];
    __shared__ float sstat;
    const int len = t + 1;

    float mx = -1e30f;
    for (int s = threadIdx.x; s < len; s += blockDim.x) {
        float v = row[s] * scale;
        buf[s] = v;
        mx = fmaxf(mx, v);
    }
    mx = warpMax(mx);
    if ((threadIdx.x & 31) == 0) red[threadIdx.x >> 5] = mx;
    __syncthreads();
    if (threadIdx.x == 0) {
        float m = -1e30f;
        #pragma unroll
        for (int i = 0; i < 8; i++) m = fmaxf(m, red[i]);
        sstat = m;
    }
    __syncthreads();
    mx = sstat;

    float sum = 0.f;
    for (int s = threadIdx.x; s < len; s += blockDim.x) {
        float e = __expf(buf[s] - mx);
        buf[s] = e;
        sum += e;
    }
    sum = warpSum(sum);
    __syncthreads();
    if ((threadIdx.x & 31) == 0) red[threadIdx.x >> 5] = sum;
    __syncthreads();
    if (threadIdx.x == 0) {
        float tt = 0.f;
        #pragma unroll
        for (int i = 0; i < 8; i++) tt += red[i];
        sstat = 1.f / tt;
    }
    __syncthreads();
    const float inv = sstat;
    for (int s = threadIdx.x; s < len; s += blockDim.x) row[s] = buf[s] * inv;
    const int zend = min(SEQ, (len + 127) & ~127);
    for (int s = len + threadIdx.x; s < zend; s += blockDim.x) row[s] = 0.f;
}

// ---------------- Host driver ----------------
static inline void launch_gemm(const float* A, const float* B, float* C,
                               int M, int N, int K, int lda, int ldb, int ldc,
                               long long aB, long long aH, long long bB, long long bH,
                               long long cB, long long cH, int Hdim, int Z, int mode)
{
    dim3 grid((N + GBN - 1) / GBN, (M + GBM - 1) / GBM, Z);
    tf32gemm_k<<<grid, 256, SMEM_GEMM_BYTES>>>(A, B, C, M, N, K, lda, ldb, ldc,
                                               aB, aH, bB, bH, cB, cH, Hdim, mode);
}

extern "C" void kernel_launch(void* const* d_in, const int* in_sizes, int n_in,
                              void* d_out, int out_size)
{
    const float* x        = (const float*)d_in[0];
    const float* fc       = (const float*)d_in[1];
    const float* fs       = (const float*)d_in[2];
    const float* q_down   = (const float*)d_in[3];
    const float* q_norm   = (const float*)d_in[4];
    const float* q_up_n   = (const float*)d_in[5];
    const float* q_up_r   = (const float*)d_in[6];
    const float* kv_down  = (const float*)d_in[7];
    const float* kv_norm  = (const float*)d_in[8];
    const float* kv_up    = (const float*)d_in[9];
    const float* qhw      = (const float*)d_in[10];
    const float* khw      = (const float*)d_in[11];
    const float* wo       = (const float*)d_in[12];
    float* out            = (float*)d_out;

    static bool attr_set = false;
    if (!attr_set) {
        cudaFuncSetAttribute(tf32gemm_k, cudaFuncAttributeMaxDynamicSharedMemorySize,
                             SMEM_GEMM_BYTES);
        attr_set = true;
    }

    float* S = nullptr;
    cudaGetSymbolAddress((void**)&S, g_scratch);

    float* CQ     = S + O_CQ;
    float* KVRAW  = S + O_KVRAW;
    float* CKV    = S + O_CKV;
    float* QN     = S + O_QN;
    float* QR     = S + O_QR;
    float* Q      = S + O_Q;
    float* KVUP   = S + O_KVUP;
    float* KT     = S + O_KT;
    float* V      = S + O_V;
    float* KROPE  = S + O_KROPE;
    float* SCORES = S + O_SCORES;
    float* ATTN   = S + O_ATTN;

    // 1) c_q = rmsnorm(x @ q_down_w)
    launch_gemm(x, q_down, CQ, NTOK, QLR, DIM, DIM, QLR, QLR,
                0, 0, 0, 0, 0, 0, 1, 1, 0);
    rmsnorm_k<<<NTOK, 256>>>(CQ, CQ, q_norm, QLR, QLR, QLR);

    // 2) kv_raw = x @ kv_down_w ; c_kv = rmsnorm(kv_raw[:, :512]) ; k_rope
    launch_gemm(x, kv_down, KVRAW, NTOK, KVLR + RD, DIM, DIM, KVLR + RD, KVLR + RD,
                0, 0, 0, 0, 0, 0, 1, 1, 0);
    rmsnorm_k<<<NTOK, 256>>>(KVRAW, CKV, kv_norm, KVLR, KVLR + RD, KVLR);
    krope_k<<<NTOK, 32>>>(KVRAW, fc, fs, KROPE);

    // 3) q_nope / q_rope projections + epilogue -> Q [tok, h, 192]
    launch_gemm(CQ, q_up_n, QN, NTOK, HEADS * ND, QLR, QLR, HEADS * ND, HEADS * ND,
                0, 0, 0, 0, 0, 0, 1, 1, 0);
    launch_gemm(CQ, q_up_r, QR, NTOK, HEADS * RD, QLR, QLR, HEADS * RD, HEADS * RD,
                0, 0, 0, 0, 0, 0, 1, 1, 0);
    q_epi_k<<<dim3(NTOK, HEADS), 128>>>(QN, QR, qhw, fc, fs, Q);

    // 4) kv up-projection + epilogue -> K^T [b,h,192,s], V [tok,h,128]
    launch_gemm(CKV, kv_up, KVUP, NTOK, HEADS * (ND + VD), KVLR,
                KVLR, HEADS * (ND + VD), HEADS * (ND + VD),
                0, 0, 0, 0, 0, 0, 1, 1, 0);
    kv_epi_k<<<dim3(NTOK, HEADS), 128>>>(KVUP, khw, KROPE, KT, V);

    // 5) scores = Q @ K^T per (b,h)  [causal tiles skipped]
    launch_gemm(Q, KT, SCORES, SEQ, SEQ, DQK,
                HEADS * DQK, SEQ, SEQ,
                (long long)SEQ * HEADS * DQK, DQK,
                (long long)HEADS * DQK * SEQ, (long long)DQK * SEQ,
                (long long)HEADS * SEQ * SEQ, (long long)SEQ * SEQ,
                HEADS, BATCH * HEADS, 1);

    // 6) scale + causal softmax (in place), zero masked tail to 128 boundary
    {
        float scale = 1.0f / sqrtf((float)DQK);
        softmax_k<<<dim3(SEQ, BATCH * HEADS), 256>>>(SCORES, scale);
    }

    // 7) attn_out[b,t,h,128] = P @ V per (b,h)   [K limited to causal extent]
    launch_gemm(SCORES, V, ATTN, SEQ, VD, SEQ,
                SEQ, HEADS * VD, HEADS * VD,
                (long long)HEADS * SEQ * SEQ, (long long)SEQ * SEQ,
                (long long)SEQ * HEADS * VD, VD,
                (long long)SEQ * HEADS * VD, VD,
                HEADS, BATCH * HEADS, 2);

    // 8) out = attn_out @ wo_w
    launch_gemm(ATTN, wo, out, NTOK, DIM, HEADS * VD,
                HEADS * VD, DIM, DIM,
                0, 0, 0, 0, 0, 0, 1, 1, 0);
}

// round 4
// speedup vs baseline: 3.5129x; 1.0593x over previous
#include <cuda_runtime.h>
#include <math.h>

// ---------------- Problem constants ----------------
#define BATCH 2
#define SEQ   2048
#define DIM   2048
#define HEADS 16
#define QLR   1536
#define KVLR  512
#define RD    64
#define ND    128
#define VD    128
#define NTOK  (BATCH*SEQ)      // 4096
#define DQK   (ND+RD)          // 192
#define EPSF  1e-6f

// ---------------- Scratch (single device global; no allocations) ----------------
#define O_CQ     ((size_t)0)
#define O_KVRAW  (O_CQ     + (size_t)NTOK*QLR)
#define O_CKV    (O_KVRAW  + (size_t)NTOK*(KVLR+RD))
#define O_QN     (O_CKV    + (size_t)NTOK*KVLR)
#define O_QR     (O_QN     + (size_t)NTOK*HEADS*ND)
#define O_Q      (O_QR     + (size_t)NTOK*HEADS*RD)
#define O_KVUP   (O_Q      + (size_t)NTOK*HEADS*DQK)
#define O_KT     (O_KVUP   + (size_t)NTOK*HEADS*(ND+VD))
#define O_V      (O_KT     + (size_t)BATCH*HEADS*DQK*SEQ)
#define O_KROPE  (O_V      + (size_t)NTOK*HEADS*VD)
#define O_SCORES (O_KROPE  + (size_t)NTOK*RD)
#define O_ATTN   (O_SCORES + (size_t)BATCH*HEADS*SEQ*SEQ)
// pre-rounded (tf32) copies of external inputs
#define O_XR     (O_ATTN   + (size_t)NTOK*HEADS*VD)
#define O_W1     (O_XR     + (size_t)NTOK*DIM)                 // q_down
#define O_W2     (O_W1     + (size_t)DIM*QLR)                  // q_up_nope
#define O_W3     (O_W2     + (size_t)QLR*HEADS*ND)             // q_up_rope
#define O_W4     (O_W3     + (size_t)QLR*HEADS*RD)             // kv_down
#define O_W5     (O_W4     + (size_t)DIM*(KVLR+RD))            // kv_up
#define O_W6     (O_W5     + (size_t)KVLR*HEADS*(ND+VD))       // wo
#define O_TOTAL  (O_W6     + (size_t)HEADS*VD*DIM)

__device__ float g_scratch[O_TOTAL];

// ---------------- Reductions ----------------
__device__ __forceinline__ float warpSum(float v) {
    #pragma unroll
    for (int o = 16; o; o >>= 1) v += __shfl_xor_sync(0xffffffffu, v, o);
    return v;
}
__device__ __forceinline__ float warpMax(float v) {
    #pragma unroll
    for (int o = 16; o; o >>= 1) v = fmaxf(v, __shfl_xor_sync(0xffffffffu, v, o));
    return v;
}

// ---------------- tf32 helpers ----------------
__device__ __forceinline__ unsigned f2tf32(float f) {
    unsigned u;
    asm("cvt.rna.tf32.f32 %0, %1;" : "=r"(u) : "f"(f));
    return u;
}
// round-to-nearest tf32, returned as an fp32 value (low 13 mantissa bits zero)
__device__ __forceinline__ float tf32r(float f) {
    return __uint_as_float(f2tf32(f));
}

__device__ __forceinline__ void mma_tf32(
    float& d0, float& d1, float& d2, float& d3,
    unsigned a0, unsigned a1, unsigned a2, unsigned a3,
    unsigned b0, unsigned b1)
{
    asm volatile(
        "mma.sync.aligned.m16n8k8.row.col.f32.tf32.tf32.f32 "
        "{%0,%1,%2,%3}, {%4,%5,%6,%7}, {%8,%9}, {%0,%1,%2,%3};"
        : "+f"(d0), "+f"(d1), "+f"(d2), "+f"(d3)
        : "r"(a0), "r"(a1), "r"(a2), "r"(a3), "r"(b0), "r"(b1));
}

// 16-byte async copy, zero-filled when pred is false
__device__ __forceinline__ void cpasync16(float* smem_dst, const float* gsrc, bool pred) {
    unsigned saddr = (unsigned)__cvta_generic_to_shared(smem_dst);
    int bytes = pred ? 16 : 0;
    asm volatile("cp.async.cg.shared.global [%0], [%1], 16, %2;\n"
                 :: "r"(saddr), "l"(gsrc), "r"(bytes));
}

// ---------------- Batched TF32 GEMM, 2-stage cp.async pipeline ----------------
// Inputs MUST be pre-rounded to tf32 (low 13 mantissa bits zero); no cvt in
// the mainloop — HMMA truncation is then exact.
// Within each 8-k MMA step s, lane quad-index tig consumes physical
// k = 8s+2*tig (lo) and 8s+2*tig+1 (hi) for BOTH A and B (k-permutation is
// sum-invariant) -> A fragment feed becomes contiguous LDS.64.
// mode 0: plain. mode 1: causal score GEMM (skip tiles above diagonal).
// mode 2: causal P@V GEMM (K limited to blockRow+GBM).
#define GBM 128
#define GBN 128
#define GBK 32
#define A_ST 40    // stride%32=8 -> A LDS.64 conflict-free (banks 8*grp pattern)
#define B_ST 132   // stride%16=4 -> B LDS.32 conflict-free (banks 8*tig+grp)
#define SMEM_GEMM_BYTES ((2*GBM*A_ST + 2*GBK*B_ST) * 4)   // 74752

__global__ void __launch_bounds__(256, 2) tf32gemm_k(
    const float* __restrict__ A, const float* __restrict__ B, float* __restrict__ C,
    int M, int N, int K, int lda, int ldb, int ldc,
    long long aB, long long aH, long long bB, long long bH, long long cB, long long cH,
    int Hdim, int mode, int roundC)
{
    extern __shared__ float dynsmem[];
    float* As = dynsmem;                       // [2][GBM][A_ST]
    float* Bs = dynsmem + 2 * GBM * A_ST;      // [2][GBK][B_ST]

    const int z = blockIdx.z;
    const int bb = z / Hdim, hh = z - bb * Hdim;
    A += (size_t)bb * aB + (size_t)hh * aH;
    B += (size_t)bb * bB + (size_t)hh * bH;
    C += (size_t)bb * cB + (size_t)hh * cH;

    const int blockRow = blockIdx.y * GBM;
    const int blockCol = blockIdx.x * GBN;
    if (mode == 1 && blockCol >= blockRow + GBM) return;   // fully masked tile
    const int Kend = (mode == 2) ? min(K, blockRow + GBM) : K;

    const int tid  = threadIdx.x;
    const int lane = tid & 31;
    const int warp = tid >> 5;
    const int tig  = lane & 3;      // thread in quad
    const int grp  = lane >> 2;     // quad id 0..7
    const int m_off = (warp >> 2) * 64;   // 2 warp-rows
    const int n_off = (warp & 3) * 32;    // 4 warp-cols

    // Per-thread chunk coordinates (4 x 16B for A, 4 x 16B for B)
    int am[4], ak[4], bk[4], bn[4];
    #pragma unroll
    for (int it = 0; it < 4; it++) {
        int v = tid + it * 256;
        am[it] = v >> 3;            // 0..127
        ak[it] = (v & 7) << 2;      // 0,4,...,28
        bk[it] = v >> 5;            // 0..31
        bn[it] = (v & 31) << 2;     // 0..124
    }

    auto load_tile = [&](int st, int k0) {
        float* Asb = As + st * GBM * A_ST;
        float* Bsb = Bs + st * GBK * B_ST;
        #pragma unroll
        for (int it = 0; it < 4; it++) {
            int gm = blockRow + am[it], gk = k0 + ak[it];
            bool p = (gm < M) && (gk < K);
            const float* src = p ? (A + (size_t)gm * lda + gk) : A;
            cpasync16(Asb + am[it] * A_ST + ak[it], src, p);
        }
        #pragma unroll
        for (int it = 0; it < 4; it++) {
            int gk = k0 + bk[it], gn = blockCol + bn[it];
            bool p = (gk < K) && (gn < N);
            const float* src = p ? (B + (size_t)gk * ldb + gn) : B;
            cpasync16(Bsb + bk[it] * B_ST + bn[it], src, p);
        }
    };

    float acc[4][4][4];
    #pragma unroll
    for (int i = 0; i < 4; i++)
        #pragma unroll
        for (int j = 0; j < 4; j++)
            #pragma unroll
            for (int r = 0; r < 4; r++) acc[i][j][r] = 0.f;

    const int nk = (Kend + GBK - 1) / GBK;

    load_tile(0, 0);
    asm volatile("cp.async.commit_group;\n" ::);

    for (int kb = 0; kb < nk; kb++) {
        if (kb + 1 < nk) {
            load_tile((kb + 1) & 1, (kb + 1) * GBK);
            asm volatile("cp.async.commit_group;\n" ::);
            asm volatile("cp.async.wait_group 1;\n" ::);
        } else {
            asm volatile("cp.async.wait_group 0;\n" ::);
        }
        __syncthreads();

        const float* Asb = As + (kb & 1) * GBM * A_ST;
        const float* Bsb = Bs + (kb & 1) * GBK * B_ST;

        #pragma unroll
        for (int s = 0; s < 4; s++) {
            const int kbase = 8 * s + 2 * tig;
            uint2 aLo[4], aHi[4];
            #pragma unroll
            for (int mt = 0; mt < 4; mt++) {
                int r0 = m_off + mt * 16 + grp;
                aLo[mt] = *(const uint2*)(Asb + r0 * A_ST + kbase);
                aHi[mt] = *(const uint2*)(Asb + (r0 + 8) * A_ST + kbase);
            }
            unsigned b0[4], b1[4];
            #pragma unroll
            for (int nt = 0; nt < 4; nt++) {
                int c0 = n_off + nt * 8 + grp;
                b0[nt] = *(const unsigned*)(Bsb + kbase * B_ST + c0);
                b1[nt] = *(const unsigned*)(Bsb + (kbase + 1) * B_ST + c0);
            }
            #pragma unroll
            for (int mt = 0; mt < 4; mt++)
                #pragma unroll
                for (int nt = 0; nt < 4; nt++)
                    mma_tf32(acc[mt][nt][0], acc[mt][nt][1], acc[mt][nt][2], acc[mt][nt][3],
                             aLo[mt].x, aHi[mt].x, aLo[mt].y, aHi[mt].y,
                             b0[nt], b1[nt]);
        }
        __syncthreads();
    }

    // ---- Epilogue ----
    #pragma unroll
    for (int mt = 0; mt < 4; mt++) {
        int r0 = blockRow + m_off + mt * 16 + grp;
        #pragma unroll
        for (int nt = 0; nt < 4; nt++) {
            int c0 = blockCol + n_off + nt * 8 + tig * 2;
            float v0 = acc[mt][nt][0], v1 = acc[mt][nt][1];
            float v2 = acc[mt][nt][2], v3 = acc[mt][nt][3];
            if (roundC) { v0 = tf32r(v0); v1 = tf32r(v1); v2 = tf32r(v2); v3 = tf32r(v3); }
            if (c0 < N) {
                if (r0 < M)
                    *(float2*)(C + (size_t)r0 * ldc + c0) = make_float2(v0, v1);
                if (r0 + 8 < M)
                    *(float2*)(C + (size_t)(r0 + 8) * ldc + c0) = make_float2(v2, v3);
            }
        }
    }
}

// ---------------- tf32 pre-round copy (for external inputs) ----------------
__global__ void roundcopy_k(const float* __restrict__ src, float* __restrict__ dst, int n)
{
    int i = (blockIdx.x * blockDim.x + threadIdx.x) * 4;
    if (i + 3 < n) {
        float4 v = *(const float4*)(src + i);
        v.x = tf32r(v.x); v.y = tf32r(v.y); v.z = tf32r(v.z); v.w = tf32r(v.w);
        *(float4*)(dst + i) = v;
    } else {
        for (int j = i; j < n; j++) dst[j] = tf32r(src[j]);
    }
}

// ---------------- Row RMSNorm (output tf32-rounded) ----------------
__global__ void rmsnorm_k(const float* __restrict__ src, float* __restrict__ dst,
                          const float* __restrict__ w, int cols, int sld, int dld)
{
    const size_t row = blockIdx.x;
    const float* s = src + row * (size_t)sld;
    float* d = dst + row * (size_t)dld;
    float ss = 0.f;
    for (int c = threadIdx.x; c < cols; c += blockDim.x) { float v = s[c]; ss += v * v; }
    __shared__ float red[8];
    __shared__ float sinv;
    ss = warpSum(ss);
    if ((threadIdx.x & 31) == 0) red[threadIdx.x >> 5] = ss;
    __syncthreads();
    if (threadIdx.x == 0) {
        float t = 0.f;
        #pragma unroll
        for (int i = 0; i < 8; i++) t += red[i];
        sinv = rsqrtf(t / cols + EPSF);
    }
    __syncthreads();
    const float inv = sinv;
    for (int c = threadIdx.x; c < cols; c += blockDim.x) d[c] = tf32r(s[c] * inv * w[c]);
}

// ---------------- k_rope precompute (output tf32-rounded) ----------------
__global__ void krope_k(const float* __restrict__ kvraw, const float* __restrict__ fc,
                        const float* __restrict__ fs, float* __restrict__ kr)
{
    const int tok = blockIdx.x, i = threadIdx.x;   // 32 threads
    if (i >= RD / 2) return;
    const int t = tok & (SEQ - 1);
    const float* r = kvraw + (size_t)tok * (KVLR + RD) + KVLR;
    float a = r[2 * i], b = r[2 * i + 1];
    float c = fc[t * (RD / 2) + i], s = fs[t * (RD / 2) + i];
    kr[(size_t)tok * RD + 2 * i]     = tf32r(a * c - b * s);
    kr[(size_t)tok * RD + 2 * i + 1] = tf32r(a * s + b * c);
}

// ---------------- Q epilogue (output tf32-rounded) ----------------
__global__ void q_epi_k(const float* __restrict__ qn, const float* __restrict__ qr,
                        const float* __restrict__ qhw,
                        const float* __restrict__ fc, const float* __restrict__ fs,
                        float* __restrict__ qout)
{
    const int tok = blockIdx.x, h = blockIdx.y, tid = threadIdx.x;  // 128 threads
    const int t = tok & (SEQ - 1);
    const float* src = qn + ((size_t)tok * HEADS + h) * ND;
    float v = src[tid];
    float ss = warpSum(v * v);
    __shared__ float red[4];
    __shared__ float sinv;
    if ((tid & 31) == 0) red[tid >> 5] = ss;
    __syncthreads();
    if (tid == 0) sinv = rsqrtf((red[0] + red[1] + red[2] + red[3]) / ND + EPSF);
    __syncthreads();
    float* dst = qout + ((size_t)tok * HEADS + h) * DQK;
    dst[tid] = tf32r(v * sinv * qhw[tid]);
    if (tid < RD / 2) {
        const float* r = qr + ((size_t)tok * HEADS + h) * RD;
        float a = r[2 * tid], b = r[2 * tid + 1];
        float c = fc[t * (RD / 2) + tid], s = fs[t * (RD / 2) + tid];
        dst[ND + 2 * tid]     = tf32r(a * c - b * s);
        dst[ND + 2 * tid + 1] = tf32r(a * s + b * c);
    }
}

// ---------------- KV epilogue (outputs tf32-rounded) ----------------
__global__ void kv_epi_k(const float* __restrict__ kvup, const float* __restrict__ khw,
                         const float* __restrict__ kr,
                         float* __restrict__ kt, float* __restrict__ vout)
{
    const int tok = blockIdx.x, h = blockIdx.y, tid = threadIdx.x;  // 128 threads
    const int b = tok >> 11;
    const int t = tok & (SEQ - 1);
    const float* src = kvup + ((size_t)tok * HEADS + h) * (ND + VD);
    float v = src[tid];
    float ss = warpSum(v * v);
    __shared__ float red[4];
    __shared__ float sinv;
    if ((tid & 31) == 0) red[tid >> 5] = ss;
    __syncthreads();
    if (tid == 0) sinv = rsqrtf((red[0] + red[1] + red[2] + red[3]) / ND + EPSF);
    __syncthreads();
    float* ktb = kt + (size_t)(b * HEADS + h) * DQK * SEQ;
    ktb[(size_t)tid * SEQ + t] = tf32r(v * sinv * khw[tid]);
    vout[((size_t)tok * HEADS + h) * VD + tid] = tf32r(src[ND + tid]);
    if (tid < RD)
        ktb[(size_t)(ND + tid) * SEQ + t] = kr[(size_t)tok * RD + tid];  // pre-rounded
}

// ---------------- Fused scale + causal mask + softmax (output tf32-rounded) ----------------
__global__ void softmax_k(float* __restrict__ scores, float scale)
{
    const int t = blockIdx.x;
    const int z = blockIdx.y;
    float* row = scores + ((size_t)z * SEQ + t) * SEQ;
    __shared__ float buf[SEQ];
    __shared__ float red[8];
    __shared__ float sstat;
    const int len = t + 1;

    float mx = -1e30f;
    for (int s = threadIdx.x; s < len; s += blockDim.x) {
        float v = row[s] * scale;
        buf[s] = v;
        mx = fmaxf(mx, v);
    }
    mx = warpMax(mx);
    if ((threadIdx.x & 31) == 0) red[threadIdx.x >> 5] = mx;
    __syncthreads();
    if (threadIdx.x == 0) {
        float m = -1e30f;
        #pragma unroll
        for (int i = 0; i < 8; i++) m = fmaxf(m, red[i]);
        sstat = m;
    }
    __syncthreads();
    mx = sstat;

    float sum = 0.f;
    for (int s = threadIdx.x; s < len; s += blockDim.x) {
        float e = __expf(buf[s] - mx);
        buf[s] = e;
        sum += e;
    }
    sum = warpSum(sum);
    __syncthreads();
    if ((threadIdx.x & 31) == 0) red[threadIdx.x >> 5] = sum;
    __syncthreads();
    if (threadIdx.x == 0) {
        float tt = 0.f;
        #pragma unroll
        for (int i = 0; i < 8; i++) tt += red[i];
        sstat = 1.f / tt;
    }
    __syncthreads();
    const float inv = sstat;
    for (int s = threadIdx.x; s < len; s += blockDim.x) row[s] = tf32r(buf[s] * inv);
    const int zend = min(SEQ, (len + 127) & ~127);
    for (int s = len + threadIdx.x; s < zend; s += blockDim.x) row[s] = 0.f;
}

// ---------------- Host driver ----------------
static inline void launch_gemm(const float* A, const float* B, float* C,
                               int M, int N, int K, int lda, int ldb, int ldc,
                               long long aB, long long aH, long long bB, long long bH,
                               long long cB, long long cH, int Hdim, int Z, int mode,
                               int roundC)
{
    dim3 grid((N + GBN - 1) / GBN, (M + GBM - 1) / GBM, Z);
    tf32gemm_k<<<grid, 256, SMEM_GEMM_BYTES>>>(A, B, C, M, N, K, lda, ldb, ldc,
                                               aB, aH, bB, bH, cB, cH, Hdim, mode, roundC);
}

static inline void launch_round(const float* src, float* dst, size_t n)
{
    int blocks = (int)((n + 1023) / 1024);
    roundcopy_k<<<blocks, 256>>>(src, dst, (int)n);
}

extern "C" void kernel_launch(void* const* d_in, const int* in_sizes, int n_in,
                              void* d_out, int out_size)
{
    const float* x        = (const float*)d_in[0];
    const float* fc       = (const float*)d_in[1];
    const float* fs       = (const float*)d_in[2];
    const float* q_down   = (const float*)d_in[3];
    const float* q_norm   = (const float*)d_in[4];
    const float* q_up_n   = (const float*)d_in[5];
    const float* q_up_r   = (const float*)d_in[6];
    const float* kv_down  = (const float*)d_in[7];
    const float* kv_norm  = (const float*)d_in[8];
    const float* kv_up    = (const float*)d_in[9];
    const float* qhw      = (const float*)d_in[10];
    const float* khw      = (const float*)d_in[11];
    const float* wo       = (const float*)d_in[12];
    float* out            = (float*)d_out;

    static bool attr_set = false;
    if (!attr_set) {
        cudaFuncSetAttribute(tf32gemm_k, cudaFuncAttributeMaxDynamicSharedMemorySize,
                             SMEM_GEMM_BYTES);
        attr_set = true;
    }

    float* S = nullptr;
    cudaGetSymbolAddress((void**)&S, g_scratch);

    float* CQ     = S + O_CQ;
    float* KVRAW  = S + O_KVRAW;
    float* CKV    = S + O_CKV;
    float* QN     = S + O_QN;
    float* QR     = S + O_QR;
    float* Q      = S + O_Q;
    float* KVUP   = S + O_KVUP;
    float* KT     = S + O_KT;
    float* V      = S + O_V;
    float* KROPE  = S + O_KROPE;
    float* SCORES = S + O_SCORES;
    float* ATTN   = S + O_ATTN;
    float* XR     = S + O_XR;
    float* W1     = S + O_W1;
    float* W2     = S + O_W2;
    float* W3     = S + O_W3;
    float* W4     = S + O_W4;
    float* W5     = S + O_W5;
    float* W6     = S + O_W6;

    // 0) pre-round external GEMM operands to tf32
    launch_round(x,       XR, (size_t)NTOK * DIM);
    launch_round(q_down,  W1, (size_t)DIM * QLR);
    launch_round(q_up_n,  W2, (size_t)QLR * HEADS * ND);
    launch_round(q_up_r,  W3, (size_t)QLR * HEADS * RD);
    launch_round(kv_down, W4, (size_t)DIM * (KVLR + RD));
    launch_round(kv_up,   W5, (size_t)KVLR * HEADS * (ND + VD));
    launch_round(wo,      W6, (size_t)HEADS * VD * DIM);

    // 1) c_q = rmsnorm(x @ q_down_w)
    launch_gemm(XR, W1, CQ, NTOK, QLR, DIM, DIM, QLR, QLR,
                0, 0, 0, 0, 0, 0, 1, 1, 0, 0);
    rmsnorm_k<<<NTOK, 256>>>(CQ, CQ, q_norm, QLR, QLR, QLR);

    // 2) kv_raw = x @ kv_down_w ; c_kv = rmsnorm(kv_raw[:, :512]) ; k_rope
    launch_gemm(XR, W4, KVRAW, NTOK, KVLR + RD, DIM, DIM, KVLR + RD, KVLR + RD,
                0, 0, 0, 0, 0, 0, 1, 1, 0, 0);
    rmsnorm_k<<<NTOK, 256>>>(KVRAW, CKV, kv_norm, KVLR, KVLR + RD, KVLR);
    krope_k<<<NTOK, 32>>>(KVRAW, fc, fs, KROPE);

    // 3) q_nope / q_rope projections + epilogue -> Q [tok, h, 192]
    launch_gemm(CQ, W2, QN, NTOK, HEADS * ND, QLR, QLR, HEADS * ND, HEADS * ND,
                0, 0, 0, 0, 0, 0, 1, 1, 0, 0);
    launch_gemm(CQ, W3, QR, NTOK, HEADS * RD, QLR, QLR, HEADS * RD, HEADS * RD,
                0, 0, 0, 0, 0, 0, 1, 1, 0, 0);
    q_epi_k<<<dim3(NTOK, HEADS), 128>>>(QN, QR, qhw, fc, fs, Q);

    // 4) kv up-projection + epilogue -> K^T [b,h,192,s], V [tok,h,128]
    launch_gemm(CKV, W5, KVUP, NTOK, HEADS * (ND + VD), KVLR,
                KVLR, HEADS * (ND + VD), HEADS * (ND + VD),
                0, 0, 0, 0, 0, 0, 1, 1, 0, 0);
    kv_epi_k<<<dim3(NTOK, HEADS), 128>>>(KVUP, khw, KROPE, KT, V);

    // 5) scores = Q @ K^T per (b,h)  [causal tiles skipped]
    launch_gemm(Q, KT, SCORES, SEQ, SEQ, DQK,
                HEADS * DQK, SEQ, SEQ,
                (long long)SEQ * HEADS * DQK, DQK,
                (long long)HEADS * DQK * SEQ, (long long)DQK * SEQ,
                (long long)HEADS * SEQ * SEQ, (long long)SEQ * SEQ,
                HEADS, BATCH * HEADS, 1, 0);

    // 6) scale + causal softmax (in place), zero masked tail to 128 boundary
    {
        float scale = 1.0f / sqrtf((float)DQK);
        softmax_k<<<dim3(SEQ, BATCH * HEADS), 256>>>(SCORES, scale);
    }

    // 7) attn_out[b,t,h,128] = P @ V per (b,h)   [K limited to causal extent]
    //    Output feeds the wo GEMM directly -> round C to tf32.
    launch_gemm(SCORES, V, ATTN, SEQ, VD, SEQ,
                SEQ, HEADS * VD, HEADS * VD,
                (long long)HEADS * SEQ * SEQ, (long long)SEQ * SEQ,
                (long long)SEQ * HEADS * VD, VD,
                (long long)SEQ * HEADS * VD, VD,
                HEADS, BATCH * HEADS, 2, 1);

    // 8) out = attn_out @ wo_w
    launch_gemm(ATTN, W6, out, NTOK, DIM, HEADS * VD,
                HEADS * VD, DIM, DIM,
                0, 0, 0, 0, 0, 0, 1, 1, 0, 0);
}

// round 9
// speedup vs baseline: 3.9764x; 1.1320x over previous
#include <cuda_runtime.h>
#include <cuda_fp16.h>
#include <math.h>
#include <stdint.h>

// ---------------- Problem constants ----------------
#define BATCH 2
#define SEQ   2048
#define DIM   2048
#define HEADS 16
#define QLR   1536
#define KVLR  512
#define RD    64
#define ND    128
#define VD    128
#define NTOK  (BATCH*SEQ)      // 4096
#define DQK   (ND+RD)          // 192
#define EPSF  1e-6f

// ---------------- Scratch: float region ----------------
#define F_CQKV   ((size_t)0)                                   // [4096, 2112] = cq | kvraw
#define F_QNR    (F_CQKV  + (size_t)NTOK*(QLR+KVLR+RD))        // [4096, 3072] = qn | qr
#define F_KVUP   (F_QNR   + (size_t)NTOK*(HEADS*ND+HEADS*RD))  // [4096, 4096]
#define F_SCORES (F_KVUP  + (size_t)NTOK*HEADS*(ND+VD))        // [32, 2048, 2048]
#define F_TOTAL  (F_SCORES+ (size_t)BATCH*HEADS*SEQ*SEQ)
__device__ float g_scratch[F_TOTAL];

// ---------------- Scratch: half region ----------------
#define H_XR     ((size_t)0)                                   // [4096, 2048]
#define H_W14    (H_XR    + (size_t)NTOK*DIM)                  // [2112, 2048]
#define H_W23    (H_W14   + (size_t)(QLR+KVLR+RD)*DIM)         // [3072, 1536]
#define H_W5     (H_W23   + (size_t)(HEADS*ND+HEADS*RD)*QLR)   // [4096, 512]
#define H_W6     (H_W5    + (size_t)HEADS*(ND+VD)*KVLR)        // [2048, 2048]
#define H_CQ     (H_W6    + (size_t)DIM*HEADS*VD)              // [4096, 1536]
#define H_CKV    (H_CQ    + (size_t)NTOK*QLR)                  // [4096, 512]
#define H_Q      (H_CKV   + (size_t)NTOK*KVLR)                 // [4096, 16, 192]
#define H_KS     (H_Q     + (size_t)NTOK*HEADS*DQK)            // [b,h,s,192]
#define H_VT     (H_KS    + (size_t)BATCH*HEADS*SEQ*DQK)       // [b,h,128,s]
#define H_KROPE  (H_VT    + (size_t)NTOK*HEADS*VD)             // [4096, 64]
#define H_P      (H_KROPE + (size_t)NTOK*RD)                   // [32, 2048, 2048]
#define H_ATTN   (H_P     + (size_t)BATCH*HEADS*SEQ*SEQ)       // [4096, 2048]
#define H_TOTAL  (H_ATTN  + (size_t)NTOK*HEADS*VD)
__device__ __half g_hscr[H_TOTAL];

// ---------------- Reductions ----------------
__device__ __forceinline__ float warpSum(float v) {
    #pragma unroll
    for (int o = 16; o; o >>= 1) v += __shfl_xor_sync(0xffffffffu, v, o);
    return v;
}
__device__ __forceinline__ float warpMax(float v) {
    #pragma unroll
    for (int o = 16; o; o >>= 1) v = fmaxf(v, __shfl_xor_sync(0xffffffffu, v, o));
    return v;
}

// ---------------- fp16 MMA (m16n8k16, fp32 accumulate) ----------------
__device__ __forceinline__ void mma_f16(
    float& d0, float& d1, float& d2, float& d3,
    unsigned a0, unsigned a1, unsigned a2, unsigned a3,
    unsigned b0, unsigned b1)
{
    asm volatile(
        "mma.sync.aligned.m16n8k16.row.col.f32.f16.f16.f32 "
        "{%0,%1,%2,%3}, {%4,%5,%6,%7}, {%8,%9}, {%0,%1,%2,%3};"
        : "+f"(d0), "+f"(d1), "+f"(d2), "+f"(d3)
        : "r"(a0), "r"(a1), "r"(a2), "r"(a3), "r"(b0), "r"(b1));
}

// 16B cp.async, zero-filled when pred false
__device__ __forceinline__ void cpasync16u(unsigned sa, const void* g, bool p) {
    int b = p ? 16 : 0;
    asm volatile("cp.async.cg.shared.global [%0], [%1], 16, %2;\n"
                 :: "r"(sa), "l"(g), "r"(b));
}
__device__ __forceinline__ uint32_t smem_to_u32(const void* p) {
    uint32_t a;
    asm("{ .reg .u64 t; cvta.to.shared.u64 t, %1; cvt.u32.u64 %0, t; }"
        : "=r"(a) : "l"(p));
    return a;
}

// ---------------- Batched FP16 GEMM, 2-stage cp.async pipeline ----------------
// C[M,N] = A[M,K] * B[N,K]^T; A,B half, K-major rows. XOR-swizzled smem tiles.
// mode 0 plain; mode 1 causal skip (scores); mode 2 causal K-trunc (P@V).
// halfC: C is __half (direct fp16 output); else float.
#define GBM 128
#define GBN 128
#define GBKH 64                            // halves per k-chunk (128 B/row)
#define TILEB (GBM * 128)                  // 16384 B
#define STAGEB (2 * TILEB)                 // A+B = 32768 B
#define SMEM_GEMM_BYTES (2 * STAGEB)       // 65536 B

__global__ void __launch_bounds__(256, 2) h16gemm_k(
    const __half* __restrict__ A, const __half* __restrict__ B, void* __restrict__ Cv,
    int M, int N, int K, int lda, int ldb, int ldc,
    long long aB, long long aH, long long bB, long long bH, long long cB, long long cH,
    int Hdim, int mode, int halfC)
{
    const int z = blockIdx.z;
    const int bb = z / Hdim, hh = z - bb * Hdim;
    A += (size_t)bb * aB + (size_t)hh * aH;
    B += (size_t)bb * bB + (size_t)hh * bH;
    const size_t coff = (size_t)bb * cB + (size_t)hh * cH;

    const int blockRow = blockIdx.y * GBM;
    const int blockCol = blockIdx.x * GBN;
    if (mode == 1 && blockCol >= blockRow + GBM) return;   // fully masked tile
    const int Kend = (mode == 2) ? min(K, blockRow + GBM) : K;
    const int nk = Kend / GBKH;                             // all K are %64 == 0

    extern __shared__ char sm[];
    const unsigned smu = smem_to_u32(sm);

    const int tid  = threadIdx.x;
    const int lane = tid & 31;
    const int warp = tid >> 5;
    const int tig  = lane & 3;            // thread in quad (0..3)
    const int grp  = lane >> 2;           // quad id (0..7)
    const int m_off = (warp >> 2) * 64;   // 2 warp-rows of 64
    const int n_off = (warp & 3) * 32;    // 4 warp-cols of 32

    auto load_tile = [&](int st, int k0) {   // k0 in halves
        const unsigned aBase = smu + st * STAGEB;
        const unsigned bBase = aBase + TILEB;
        #pragma unroll
        for (int it = 0; it < 4; it++) {
            int v   = tid + it * 256;          // 0..1023
            int row = v >> 3;                  // 0..127
            int c16 = v & 7;
            unsigned sw = (unsigned)(row * 128 + ((c16 * 16) ^ ((row & 7) << 4)));
            {   // A
                int gm = blockRow + row;
                bool p = gm < M;
                const __half* src = p ? (A + (size_t)gm * lda + k0 + c16 * 8) : A;
                cpasync16u(aBase + sw, src, p);
            }
            {   // B (rows are N-indices)
                int gn = blockCol + row;
                bool p = gn < N;
                const __half* src = p ? (B + (size_t)gn * ldb + k0 + c16 * 8) : B;
                cpasync16u(bBase + sw, src, p);
            }
        }
        asm volatile("cp.async.commit_group;\n" ::);
    };

    float acc[4][4][4];
    #pragma unroll
    for (int i = 0; i < 4; i++)
        #pragma unroll
        for (int j = 0; j < 4; j++)
            #pragma unroll
            for (int r = 0; r < 4; r++) acc[i][j][r] = 0.f;

    load_tile(0, 0);

    for (int kb = 0; kb < nk; kb++) {
        if (kb + 1 < nk) {
            load_tile((kb + 1) & 1, (kb + 1) * GBKH);
            asm volatile("cp.async.wait_group 1;\n" ::);
        } else {
            asm volatile("cp.async.wait_group 0;\n" ::);
        }
        __syncthreads();

        const char* Asb = sm + (kb & 1) * STAGEB;
        const char* Bsb = Asb + TILEB;
        const int swA = (grp << 4);

        #pragma unroll
        for (int ks = 0; ks < 4; ks++) {       // 4 k-steps of 16 halves
            const int c0 = (32 * ks + 4 * tig) ^ swA;        // bytes, k low 8
            const int c2 = (32 * ks + 4 * tig + 16) ^ swA;   // bytes, k high 8
            unsigned af[4][4], bf[4][2];
            #pragma unroll
            for (int mt = 0; mt < 4; mt++) {
                const char* rp = Asb + (m_off + mt * 16 + grp) * 128;
                af[mt][0] = *(const unsigned*)(rp + c0);
                af[mt][1] = *(const unsigned*)(rp + 1024 + c0);   // row +8
                af[mt][2] = *(const unsigned*)(rp + c2);
                af[mt][3] = *(const unsigned*)(rp + 1024 + c2);
            }
            #pragma unroll
            for (int nt = 0; nt < 4; nt++) {
                const char* np = Bsb + (n_off + nt * 8 + grp) * 128;
                bf[nt][0] = *(const unsigned*)(np + c0);
                bf[nt][1] = *(const unsigned*)(np + c2);
            }
            #pragma unroll
            for (int mt = 0; mt < 4; mt++)
                #pragma unroll
                for (int nt = 0; nt < 4; nt++)
                    mma_f16(acc[mt][nt][0], acc[mt][nt][1], acc[mt][nt][2], acc[mt][nt][3],
                            af[mt][0], af[mt][1], af[mt][2], af[mt][3],
                            bf[nt][0], bf[nt][1]);
        }
        __syncthreads();
    }

    // ---- Epilogue ----
    if (halfC) {
        __half* C = (__half*)Cv + coff;
        #pragma unroll
        for (int mt = 0; mt < 4; mt++) {
            int r0 = blockRow + m_off + mt * 16 + grp;
            #pragma unroll
            for (int nt = 0; nt < 4; nt++) {
                int c0 = blockCol + n_off + nt * 8 + tig * 2;
                if (c0 < N) {
                    if (r0 < M)
                        *(__half2*)(C + (size_t)r0 * ldc + c0) =
                            __floats2half2_rn(acc[mt][nt][0], acc[mt][nt][1]);
                    if (r0 + 8 < M)
                        *(__half2*)(C + (size_t)(r0 + 8) * ldc + c0) =
                            __floats2half2_rn(acc[mt][nt][2], acc[mt][nt][3]);
                }
            }
        }
    } else {
        float* C = (float*)Cv + coff;
        #pragma unroll
        for (int mt = 0; mt < 4; mt++) {
            int r0 = blockRow + m_off + mt * 16 + grp;
            #pragma unroll
            for (int nt = 0; nt < 4; nt++) {
                int c0 = blockCol + n_off + nt * 8 + tig * 2;
                if (c0 < N) {
                    if (r0 < M)
                        *(float2*)(C + (size_t)r0 * ldc + c0) =
                            make_float2(acc[mt][nt][0], acc[mt][nt][1]);
                    if (r0 + 8 < M)
                        *(float2*)(C + (size_t)(r0 + 8) * ldc + c0) =
                            make_float2(acc[mt][nt][2], acc[mt][nt][3]);
                }
            }
        }
    }
}

// ---------------- transpose: dst[c][r] = half(src[r][c]), dst ld = R ----------------
__global__ void transpose_h_k(const float* __restrict__ src, __half* __restrict__ dst,
                              int R, int Ccols)
{
    __shared__ float t[32][33];
    int bx = blockIdx.x * 32, by = blockIdx.y * 32;
    int x = bx + threadIdx.x;
    #pragma unroll
    for (int i = 0; i < 32; i += 8) {
        int y = by + threadIdx.y + i;
        if (x < Ccols && y < R) t[threadIdx.y + i][threadIdx.x] = src[(size_t)y * Ccols + x];
    }
    __syncthreads();
    x = by + threadIdx.x;                 // r index
    #pragma unroll
    for (int i = 0; i < 32; i += 8) {
        int y = bx + threadIdx.y + i;     // c index
        if (x < R && y < Ccols) dst[(size_t)y * R + x] = __float2half(t[threadIdx.x][threadIdx.y + i]);
    }
}

// ---------------- float -> half copy ----------------
__global__ void halfcopy_k(const float* __restrict__ src, __half* __restrict__ dst, int n)
{
    int i = (blockIdx.x * blockDim.x + threadIdx.x) * 4;
    if (i + 3 < n) {
        float4 v = *(const float4*)(src + i);
        *(__half2*)(dst + i)     = __floats2half2_rn(v.x, v.y);
        *(__half2*)(dst + i + 2) = __floats2half2_rn(v.z, v.w);
    } else {
        for (int j = i; j < n; j++) dst[j] = __float2half(src[j]);
    }
}

// ---------------- Row RMSNorm: float in (strided), half out ----------------
__global__ void rmsnorm_k(const float* __restrict__ src, __half* __restrict__ dst,
                          const float* __restrict__ w, int cols, int sld, int dld)
{
    const size_t row = blockIdx.x;
    const float* s = src + row * (size_t)sld;
    __half* d = dst + row * (size_t)dld;
    float ss = 0.f;
    for (int c = threadIdx.x; c < cols; c += blockDim.x) { float v = s[c]; ss += v * v; }
    __shared__ float red[8];
    __shared__ float sinv;
    ss = warpSum(ss);
    if ((threadIdx.x & 31) == 0) red[threadIdx.x >> 5] = ss;
    __syncthreads();
    if (threadIdx.x == 0) {
        float t = 0.f;
        #pragma unroll
        for (int i = 0; i < 8; i++) t += red[i];
        sinv = rsqrtf(t / cols + EPSF);
    }
    __syncthreads();
    const float inv = sinv;
    for (int c = threadIdx.x; c < cols; c += blockDim.x)
        d[c] = __float2half(s[c] * inv * w[c]);
}

// ---------------- k_rope precompute (half out) ----------------
__global__ void krope_k(const float* __restrict__ cqkv, const float* __restrict__ fc,
                        const float* __restrict__ fs, __half* __restrict__ kr)
{
    const int tok = blockIdx.x, i = threadIdx.x;   // 32 threads
    if (i >= RD / 2) return;
    const int t = tok & (SEQ - 1);
    const float* r = cqkv + (size_t)tok * (QLR + KVLR + RD) + QLR + KVLR;
    float a = r[2 * i], b = r[2 * i + 1];
    float c = fc[t * (RD / 2) + i], s = fs[t * (RD / 2) + i];
    kr[(size_t)tok * RD + 2 * i]     = __float2half(a * c - b * s);
    kr[(size_t)tok * RD + 2 * i + 1] = __float2half(a * s + b * c);
}

// ---------------- Q epilogue: QNR float -> Q half [tok,h,192] ----------------
__global__ void q_epi_k(const float* __restrict__ qnr, const float* __restrict__ qhw,
                        const float* __restrict__ fc, const float* __restrict__ fs,
                        __half* __restrict__ qout)
{
    const int tok = blockIdx.x, h = blockIdx.y, tid = threadIdx.x;  // 128 threads
    const int t = tok & (SEQ - 1);
    const float* src = qnr + (size_t)tok * (HEADS * ND + HEADS * RD) + (size_t)h * ND;
    float v = src[tid];
    float ss = warpSum(v * v);
    __shared__ float red[4];
    __shared__ float sinv;
    if ((tid & 31) == 0) red[tid >> 5] = ss;
    __syncthreads();
    if (tid == 0) sinv = rsqrtf((red[0] + red[1] + red[2] + red[3]) / ND + EPSF);
    __syncthreads();
    __half* dst = qout + ((size_t)tok * HEADS + h) * DQK;
    dst[tid] = __float2half(v * sinv * qhw[tid]);
    if (tid < RD / 2) {
        const float* r = qnr + (size_t)tok * (HEADS * ND + HEADS * RD)
                       + (size_t)HEADS * ND + (size_t)h * RD;
        float a = r[2 * tid], b = r[2 * tid + 1];
        float c = fc[t * (RD / 2) + tid], s = fs[t * (RD / 2) + tid];
        dst[ND + 2 * tid]     = __float2half(a * c - b * s);
        dst[ND + 2 * tid + 1] = __float2half(a * s + b * c);
    }
}

// ---------------- KV epilogue: KS half [b,h,s,192], V^T half [b,h,128,s] ----------------
__global__ void kv_epi_k(const float* __restrict__ kvup, const float* __restrict__ khw,
                         const __half* __restrict__ kr,
                         __half* __restrict__ ks, __half* __restrict__ vt)
{
    const int tok = blockIdx.x, h = blockIdx.y, tid = threadIdx.x;  // 128 threads
    const int b = tok >> 11;
    const int t = tok & (SEQ - 1);
    const float* src = kvup + ((size_t)tok * HEADS + h) * (ND + VD);
    float v = src[tid];
    float ss = warpSum(v * v);
    __shared__ float red[4];
    __shared__ float sinv;
    if ((tid & 31) == 0) red[tid >> 5] = ss;
    __syncthreads();
    if (tid == 0) sinv = rsqrtf((red[0] + red[1] + red[2] + red[3]) / ND + EPSF);
    __syncthreads();
    __half* ksb = ks + ((size_t)(b * HEADS + h) * SEQ + t) * DQK;
    ksb[tid] = __float2half(v * sinv * khw[tid]);
    vt[((size_t)(b * HEADS + h) * VD + tid) * SEQ + t] = __float2half(src[ND + tid]);
    if (tid < RD)
        ksb[ND + tid] = kr[(size_t)tok * RD + tid];   // already half
}

// ---------------- scale + causal softmax: SCORES float -> P half ----------------
__global__ void softmax_k(const float* __restrict__ scores, __half* __restrict__ P,
                          float scale)
{
    const int t = blockIdx.x;
    const int z = blockIdx.y;
    const float* row = scores + ((size_t)z * SEQ + t) * SEQ;
    __half* prow = P + ((size_t)z * SEQ + t) * SEQ;
    __shared__ float buf[SEQ];
    __shared__ float red[8];
    __shared__ float sstat;
    const int len = t + 1;

    float mx = -1e30f;
    for (int s = threadIdx.x; s < len; s += blockDim.x) {
        float v = row[s] * scale;
        buf[s] = v;
        mx = fmaxf(mx, v);
    }
    mx = warpMax(mx);
    if ((threadIdx.x & 31) == 0) red[threadIdx.x >> 5] = mx;
    __syncthreads();
    if (threadIdx.x == 0) {
        float m = -1e30f;
        #pragma unroll
        for (int i = 0; i < 8; i++) m = fmaxf(m, red[i]);
        sstat = m;
    }
    __syncthreads();
    mx = sstat;

    float sum = 0.f;
    for (int s = threadIdx.x; s < len; s += blockDim.x) {
        float e = __expf(buf[s] - mx);
        buf[s] = e;
        sum += e;
    }
    sum = warpSum(sum);
    __syncthreads();
    if ((threadIdx.x & 31) == 0) red[threadIdx.x >> 5] = sum;
    __syncthreads();
    if (threadIdx.x == 0) {
        float tt = 0.f;
        #pragma unroll
        for (int i = 0; i < 8; i++) tt += red[i];
        sstat = 1.f / tt;
    }
    __syncthreads();
    const float inv = sstat;
    for (int s = threadIdx.x; s < len; s += blockDim.x)
        prow[s] = __float2half(buf[s] * inv);
    const int zend = min(SEQ, (len + 127) & ~127);   // P@V reads to 128 boundary
    for (int s = len + threadIdx.x; s < zend; s += blockDim.x)
        prow[s] = __float2half(0.f);
}

// ---------------- Host driver ----------------
static inline void launch_gemm(const __half* A, const __half* B, void* C,
                               int M, int N, int K, int lda, int ldb, int ldc,
                               long long aB, long long aH, long long bB, long long bH,
                               long long cB, long long cH, int Hdim, int Z, int mode,
                               int halfC)
{
    dim3 grid((N + GBN - 1) / GBN, (M + GBM - 1) / GBM, Z);
    h16gemm_k<<<grid, 256, SMEM_GEMM_BYTES>>>(A, B, C, M, N, K, lda, ldb, ldc,
                                              aB, aH, bB, bH, cB, cH, Hdim, mode, halfC);
}

static inline void launch_transpose(const float* src, __half* dst, int R, int C)
{
    dim3 grid((C + 31) / 32, (R + 31) / 32);
    transpose_h_k<<<grid, dim3(32, 8)>>>(src, dst, R, C);
}

extern "C" void kernel_launch(void* const* d_in, const int* in_sizes, int n_in,
                              void* d_out, int out_size)
{
    const float* x        = (const float*)d_in[0];
    const float* fc       = (const float*)d_in[1];
    const float* fs       = (const float*)d_in[2];
    const float* q_down   = (const float*)d_in[3];
    const float* q_norm   = (const float*)d_in[4];
    const float* q_up_n   = (const float*)d_in[5];
    const float* q_up_r   = (const float*)d_in[6];
    const float* kv_down  = (const float*)d_in[7];
    const float* kv_norm  = (const float*)d_in[8];
    const float* kv_up    = (const float*)d_in[9];
    const float* qhw      = (const float*)d_in[10];
    const float* khw      = (const float*)d_in[11];
    const float* wo       = (const float*)d_in[12];
    float* out            = (float*)d_out;

    static bool attr_set = false;
    if (!attr_set) {
        cudaFuncSetAttribute(h16gemm_k, cudaFuncAttributeMaxDynamicSharedMemorySize,
                             SMEM_GEMM_BYTES);
        attr_set = true;
    }

    float* F = nullptr;
    __half* H = nullptr;
    cudaGetSymbolAddress((void**)&F, g_scratch);
    cudaGetSymbolAddress((void**)&H, g_hscr);

    float* CQKV   = F + F_CQKV;
    float* QNR    = F + F_QNR;
    float* KVUP   = F + F_KVUP;
    float* SCORES = F + F_SCORES;

    __half* XR    = H + H_XR;
    __half* W14   = H + H_W14;
    __half* W23   = H + H_W23;
    __half* W5    = H + H_W5;
    __half* W6    = H + H_W6;
    __half* CQ    = H + H_CQ;
    __half* CKV   = H + H_CKV;
    __half* Q     = H + H_Q;
    __half* KS    = H + H_KS;
    __half* VT    = H + H_VT;
    __half* KROPE = H + H_KROPE;
    __half* P     = H + H_P;
    __half* ATTN  = H + H_ATTN;

    const int NW14 = QLR + KVLR + RD;          // 2112
    const int NW23 = HEADS * ND + HEADS * RD;  // 3072

    // 0) convert x to half; transpose weights to [N, K] half
    {
        size_t n = (size_t)NTOK * DIM;
        halfcopy_k<<<(int)((n + 1023) / 1024), 256>>>(x, XR, (int)n);
    }
    launch_transpose(q_down,  W14,                      DIM,  QLR);       // rows 0..1535
    launch_transpose(kv_down, W14 + (size_t)QLR * DIM,  DIM,  KVLR + RD); // rows 1536..2111
    launch_transpose(q_up_n,  W23,                      QLR,  HEADS * ND);
    launch_transpose(q_up_r,  W23 + (size_t)HEADS * ND * QLR, QLR, HEADS * RD);
    launch_transpose(kv_up,   W5,  KVLR, HEADS * (ND + VD));
    launch_transpose(wo,      W6,  HEADS * VD, DIM);

    // 1) [c_q | kv_raw] = x @ [q_down | kv_down]   (merged)
    launch_gemm(XR, W14, CQKV, NTOK, NW14, DIM, DIM, DIM, NW14,
                0, 0, 0, 0, 0, 0, 1, 1, 0, 0);
    rmsnorm_k<<<NTOK, 256>>>(CQKV,        CQ,  q_norm,  QLR,  NW14, QLR);
    rmsnorm_k<<<NTOK, 256>>>(CQKV + QLR,  CKV, kv_norm, KVLR, NW14, KVLR);
    krope_k<<<NTOK, 32>>>(CQKV, fc, fs, KROPE);

    // 2) [q_nope | q_rope] = c_q @ [q_up_n | q_up_r]   (merged) + epilogue
    launch_gemm(CQ, W23, QNR, NTOK, NW23, QLR, QLR, QLR, NW23,
                0, 0, 0, 0, 0, 0, 1, 1, 0, 0);
    q_epi_k<<<dim3(NTOK, HEADS), 128>>>(QNR, qhw, fc, fs, Q);

    // 3) kv up-projection + epilogue -> KS, VT
    launch_gemm(CKV, W5, KVUP, NTOK, HEADS * (ND + VD), KVLR,
                KVLR, KVLR, HEADS * (ND + VD),
                0, 0, 0, 0, 0, 0, 1, 1, 0, 0);
    kv_epi_k<<<dim3(NTOK, HEADS), 128>>>(KVUP, khw, KROPE, KS, VT);

    // 4) scores = Q @ K^T per (b,h)  [causal tiles skipped]
    launch_gemm(Q, KS, SCORES, SEQ, SEQ, DQK,
                HEADS * DQK, DQK, SEQ,
                (long long)SEQ * HEADS * DQK, DQK,
                (long long)HEADS * SEQ * DQK, (long long)SEQ * DQK,
                (long long)HEADS * SEQ * SEQ, (long long)SEQ * SEQ,
                HEADS, BATCH * HEADS, 1, 0);

    // 5) scale + causal softmax -> P (half)
    {
        float scale = 1.0f / sqrtf((float)DQK);
        softmax_k<<<dim3(SEQ, BATCH * HEADS), 256>>>(SCORES, P, scale);
    }

    // 6) attn_out = P @ V per (b,h)  [K-trunc; direct half output]
    launch_gemm(P, VT, ATTN, SEQ, VD, SEQ,
                SEQ, SEQ, HEADS * VD,
                (long long)HEADS * SEQ * SEQ, (long long)SEQ * SEQ,
                (long long)HEADS * VD * SEQ, (long long)VD * SEQ,
                (long long)SEQ * HEADS * VD, VD,
                HEADS, BATCH * HEADS, 2, 1);

    // 7) out = attn_out @ wo_w
    launch_gemm(ATTN, W6, out, NTOK, DIM, HEADS * VD,
                HEADS * VD, HEADS * VD, DIM,
                0, 0, 0, 0, 0, 0, 1, 1, 0, 0);
}

// round 11
// speedup vs baseline: 6.1537x; 1.5475x over previous
#include <cuda_runtime.h>
#include <cuda_fp16.h>
#include <math.h>
#include <stdint.h>

// ---------------- Problem constants ----------------
#define BATCH 2
#define SEQ   2048
#define DIM   2048
#define HEADS 16
#define QLR   1536
#define KVLR  512
#define RD    64
#define ND    128
#define VD    128
#define NTOK  (BATCH*SEQ)      // 4096
#define DQK   (ND+RD)          // 192
#define EPSF  1e-6f

// ---------------- Scratch: float region ----------------
#define F_CQKV   ((size_t)0)                                   // [4096, 2112] = cq | kvraw
#define F_QNR    (F_CQKV  + (size_t)NTOK*(QLR+KVLR+RD))        // [4096, 3072] = qn | qr
#define F_KVUP   (F_QNR   + (size_t)NTOK*(HEADS*ND+HEADS*RD))  // [4096, 4096]
#define F_SCORES (F_KVUP  + (size_t)NTOK*HEADS*(ND+VD))        // [32, 2048, 2048]
#define F_TOTAL  (F_SCORES+ (size_t)BATCH*HEADS*SEQ*SEQ)
__device__ float g_scratch[F_TOTAL];

// ---------------- Scratch: half region ----------------
#define H_XR     ((size_t)0)                                   // [4096, 2048]
#define H_W14    (H_XR    + (size_t)NTOK*DIM)                  // [2112, 2048]
#define H_W23    (H_W14   + (size_t)(QLR+KVLR+RD)*DIM)         // [3072, 1536]
#define H_W5     (H_W23   + (size_t)(HEADS*ND+HEADS*RD)*QLR)   // [4096, 512]
#define H_W6     (H_W5    + (size_t)HEADS*(ND+VD)*KVLR)        // [2048, 2048]
#define H_CQ     (H_W6    + (size_t)DIM*HEADS*VD)              // [4096, 1536]
#define H_CKV    (H_CQ    + (size_t)NTOK*QLR)                  // [4096, 512]
#define H_Q      (H_CKV   + (size_t)NTOK*KVLR)                 // [4096, 16, 192]
#define H_KS     (H_Q     + (size_t)NTOK*HEADS*DQK)            // [b,h,s,192]
#define H_VT     (H_KS    + (size_t)BATCH*HEADS*SEQ*DQK)       // [b,h,128,s]
#define H_KROPE  (H_VT    + (size_t)NTOK*HEADS*VD)             // [4096, 64]
#define H_P      (H_KROPE + (size_t)NTOK*RD)                   // [32, 2048, 2048]
#define H_ATTN   (H_P     + (size_t)BATCH*HEADS*SEQ*SEQ)       // [4096, 2048]
#define H_TOTAL  (H_ATTN  + (size_t)NTOK*HEADS*VD)
__device__ __half g_hscr[H_TOTAL];

// ---------------- Reductions ----------------
__device__ __forceinline__ float warpSum(float v) {
    #pragma unroll
    for (int o = 16; o; o >>= 1) v += __shfl_xor_sync(0xffffffffu, v, o);
    return v;
}
__device__ __forceinline__ float warpMax(float v) {
    #pragma unroll
    for (int o = 16; o; o >>= 1) v = fmaxf(v, __shfl_xor_sync(0xffffffffu, v, o));
    return v;
}

// ---------------- fp16 MMA (m16n8k16, fp32 accumulate) ----------------
__device__ __forceinline__ void mma_f16(
    float& d0, float& d1, float& d2, float& d3,
    unsigned a0, unsigned a1, unsigned a2, unsigned a3,
    unsigned b0, unsigned b1)
{
    asm volatile(
        "mma.sync.aligned.m16n8k16.row.col.f32.f16.f16.f32 "
        "{%0,%1,%2,%3}, {%4,%5,%6,%7}, {%8,%9}, {%0,%1,%2,%3};"
        : "+f"(d0), "+f"(d1), "+f"(d2), "+f"(d3)
        : "r"(a0), "r"(a1), "r"(a2), "r"(a3), "r"(b0), "r"(b1));
}

// ldmatrix x4 (four 8x8 b16 tiles; per-lane row address)
__device__ __forceinline__ void ldsm_x4(unsigned& r0, unsigned& r1,
                                        unsigned& r2, unsigned& r3, uint32_t a)
{
    asm volatile("ldmatrix.sync.aligned.m8n8.x4.shared.b16 {%0,%1,%2,%3}, [%4];"
                 : "=r"(r0), "=r"(r1), "=r"(r2), "=r"(r3) : "r"(a));
}

// 16B cp.async, zero-filled when pred false
__device__ __forceinline__ void cpasync16u(unsigned sa, const void* g, bool p) {
    int b = p ? 16 : 0;
    asm volatile("cp.async.cg.shared.global [%0], [%1], 16, %2;\n"
                 :: "r"(sa), "l"(g), "r"(b));
}
__device__ __forceinline__ uint32_t smem_to_u32(const void* p) {
    uint32_t a;
    asm("{ .reg .u64 t; cvta.to.shared.u64 t, %1; cvt.u32.u64 %0, t; }"
        : "=r"(a) : "l"(p));
    return a;
}

// ---------------- Batched FP16 GEMM, 2-stage cp.async + ldmatrix ----------------
// C[M,N] = A[M,K] * B[N,K]^T; A,B half, K-major rows. XOR-swizzled smem tiles.
// mode 0 plain; mode 1 causal skip (scores); mode 2 causal K-trunc (P@V).
// halfC: C is __half (direct fp16 output); else float.
#define GBM 128
#define GBN 128
#define GBKH 64                            // halves per k-chunk (128 B/row)
#define TILEB (GBM * 128)                  // 16384 B
#define STAGEB (2 * TILEB)                 // A+B = 32768 B
#define SMEM_GEMM_BYTES (2 * STAGEB)       // 65536 B

__global__ void __launch_bounds__(256, 2) h16gemm_k(
    const __half* __restrict__ A, const __half* __restrict__ B, void* __restrict__ Cv,
    int M, int N, int K, int lda, int ldb, int ldc,
    long long aB, long long aH, long long bB, long long bH, long long cB, long long cH,
    int Hdim, int mode, int halfC)
{
    const int z = blockIdx.z;
    const int bb = z / Hdim, hh = z - bb * Hdim;
    A += (size_t)bb * aB + (size_t)hh * aH;
    B += (size_t)bb * bB + (size_t)hh * bH;
    const size_t coff = (size_t)bb * cB + (size_t)hh * cH;

    const int blockRow = blockIdx.y * GBM;
    const int blockCol = blockIdx.x * GBN;
    if (mode == 1 && blockCol >= blockRow + GBM) return;   // fully masked tile
    const int Kend = (mode == 2) ? min(K, blockRow + GBM) : K;
    const int nk = Kend / GBKH;                             // all K are %64 == 0

    extern __shared__ char sm[];
    const unsigned smu = smem_to_u32(sm);

    const int tid  = threadIdx.x;
    const int lane = tid & 31;
    const int warp = tid >> 5;
    const int tig  = lane & 3;            // thread in quad (0..3)
    const int grp  = lane >> 2;           // quad id (0..7)
    const int m_off = (warp >> 2) * 64;   // 2 warp-rows of 64
    const int n_off = (warp & 3) * 32;    // 4 warp-cols of 32

    // ldmatrix per-lane addressing components (matid = lane>>3, rowin = lane&7)
    const int rowin = lane & 7;
    const unsigned swz = (unsigned)(rowin << 4);
    // A x4: matrices {m+0,k+0},{m+8,k+0},{m+0,k16},{m+8,k16}
    const int a_m  = m_off + (((lane >> 3) & 1) << 3) + rowin;
    const unsigned a_hi = (unsigned)((lane >> 4) << 4);
    // B x4 (pair of n-tiles): matrices {n+0,k+0},{n+0,k16},{n+8,k+0},{n+8,k16}
    const int b_n  = n_off + ((lane >> 4) << 3) + rowin;
    const unsigned b_hi = (unsigned)(((lane >> 3) & 1) << 4);

    unsigned a_row[4], b_row[2];
    #pragma unroll
    for (int mt = 0; mt < 4; mt++) a_row[mt] = (unsigned)((a_m + mt * 16) * 128);
    #pragma unroll
    for (int np = 0; np < 2; np++) b_row[np] = (unsigned)((b_n + np * 16) * 128);

    auto load_tile = [&](int st, int k0) {   // k0 in halves
        const unsigned aBase = smu + st * STAGEB;
        const unsigned bBase = aBase + TILEB;
        #pragma unroll
        for (int it = 0; it < 4; it++) {
            int v   = tid + it * 256;          // 0..1023
            int row = v >> 3;                  // 0..127
            int c16 = v & 7;
            unsigned sw = (unsigned)(row * 128 + ((c16 * 16) ^ ((row & 7) << 4)));
            {   // A
                int gm = blockRow + row;
                bool p = gm < M;
                const __half* src = p ? (A + (size_t)gm * lda + k0 + c16 * 8) : A;
                cpasync16u(aBase + sw, src, p);
            }
            {   // B (rows are N-indices)
                int gn = blockCol + row;
                bool p = gn < N;
                const __half* src = p ? (B + (size_t)gn * ldb + k0 + c16 * 8) : B;
                cpasync16u(bBase + sw, src, p);
            }
        }
        asm volatile("cp.async.commit_group;\n" ::);
    };

    float acc[4][4][4];
    #pragma unroll
    for (int i = 0; i < 4; i++)
        #pragma unroll
        for (int j = 0; j < 4; j++)
            #pragma unroll
            for (int r = 0; r < 4; r++) acc[i][j][r] = 0.f;

    load_tile(0, 0);

    for (int kb = 0; kb < nk; kb++) {
        if (kb + 1 < nk) {
            load_tile((kb + 1) & 1, (kb + 1) * GBKH);
            asm volatile("cp.async.wait_group 1;\n" ::);
        } else {
            asm volatile("cp.async.wait_group 0;\n" ::);
        }
        __syncthreads();

        const unsigned Abase = smu + (kb & 1) * STAGEB;
        const unsigned Bbase = Abase + TILEB;

        #pragma unroll
        for (int ks = 0; ks < 4; ks++) {       // 4 k-steps of 16 halves
            const unsigned kb32 = (unsigned)(32 * ks);
            unsigned af[4][4], bf[4][2];
            #pragma unroll
            for (int mt = 0; mt < 4; mt++)
                ldsm_x4(af[mt][0], af[mt][1], af[mt][2], af[mt][3],
                        Abase + a_row[mt] + ((kb32 + a_hi) ^ swz));
            #pragma unroll
            for (int np = 0; np < 2; np++)
                ldsm_x4(bf[2*np][0], bf[2*np][1], bf[2*np+1][0], bf[2*np+1][1],
                        Bbase + b_row[np] + ((kb32 + b_hi) ^ swz));
            #pragma unroll
            for (int mt = 0; mt < 4; mt++)
                #pragma unroll
                for (int nt = 0; nt < 4; nt++)
                    mma_f16(acc[mt][nt][0], acc[mt][nt][1], acc[mt][nt][2], acc[mt][nt][3],
                            af[mt][0], af[mt][1], af[mt][2], af[mt][3],
                            bf[nt][0], bf[nt][1]);
        }
        __syncthreads();
    }

    // ---- Epilogue ----
    if (halfC) {
        __half* C = (__half*)Cv + coff;
        #pragma unroll
        for (int mt = 0; mt < 4; mt++) {
            int r0 = blockRow + m_off + mt * 16 + grp;
            #pragma unroll
            for (int nt = 0; nt < 4; nt++) {
                int c0 = blockCol + n_off + nt * 8 + tig * 2;
                if (c0 < N) {
                    if (r0 < M)
                        *(__half2*)(C + (size_t)r0 * ldc + c0) =
                            __floats2half2_rn(acc[mt][nt][0], acc[mt][nt][1]);
                    if (r0 + 8 < M)
                        *(__half2*)(C + (size_t)(r0 + 8) * ldc + c0) =
                            __floats2half2_rn(acc[mt][nt][2], acc[mt][nt][3]);
                }
            }
        }
    } else {
        float* C = (float*)Cv + coff;
        #pragma unroll
        for (int mt = 0; mt < 4; mt++) {
            int r0 = blockRow + m_off + mt * 16 + grp;
            #pragma unroll
            for (int nt = 0; nt < 4; nt++) {
                int c0 = blockCol + n_off + nt * 8 + tig * 2;
                if (c0 < N) {
                    if (r0 < M)
                        *(float2*)(C + (size_t)r0 * ldc + c0) =
                            make_float2(acc[mt][nt][0], acc[mt][nt][1]);
                    if (r0 + 8 < M)
                        *(float2*)(C + (size_t)(r0 + 8) * ldc + c0) =
                            make_float2(acc[mt][nt][2], acc[mt][nt][3]);
                }
            }
        }
    }
}

// ---------------- transpose: dst[c][r] = half(src[r][c]), dst ld = R ----------------
__global__ void transpose_h_k(const float* __restrict__ src, __half* __restrict__ dst,
                              int R, int Ccols)
{
    __shared__ float t[32][33];
    int bx = blockIdx.x * 32, by = blockIdx.y * 32;
    int x = bx + threadIdx.x;
    #pragma unroll
    for (int i = 0; i < 32; i += 8) {
        int y = by + threadIdx.y + i;
        if (x < Ccols && y < R) t[threadIdx.y + i][threadIdx.x] = src[(size_t)y * Ccols + x];
    }
    __syncthreads();
    x = by + threadIdx.x;                 // r index
    #pragma unroll
    for (int i = 0; i < 32; i += 8) {
        int y = bx + threadIdx.y + i;     // c index
        if (x < R && y < Ccols) dst[(size_t)y * R + x] = __float2half(t[threadIdx.x][threadIdx.y + i]);
    }
}

// ---------------- float -> half copy ----------------
__global__ void halfcopy_k(const float* __restrict__ src, __half* __restrict__ dst, int n)
{
    int i = (blockIdx.x * blockDim.x + threadIdx.x) * 4;
    if (i + 3 < n) {
        float4 v = *(const float4*)(src + i);
        *(__half2*)(dst + i)     = __floats2half2_rn(v.x, v.y);
        *(__half2*)(dst + i + 2) = __floats2half2_rn(v.z, v.w);
    } else {
        for (int j = i; j < n; j++) dst[j] = __float2half(src[j]);
    }
}

// ---------------- Row RMSNorm: float in (strided), half out ----------------
__global__ void rmsnorm_k(const float* __restrict__ src, __half* __restrict__ dst,
                          const float* __restrict__ w, int cols, int sld, int dld)
{
    const size_t row = blockIdx.x;
    const float* s = src + row * (size_t)sld;
    __half* d = dst + row * (size_t)dld;
    float ss = 0.f;
    for (int c = threadIdx.x; c < cols; c += blockDim.x) { float v = s[c]; ss += v * v; }
    __shared__ float red[8];
    __shared__ float sinv;
    ss = warpSum(ss);
    if ((threadIdx.x & 31) == 0) red[threadIdx.x >> 5] = ss;
    __syncthreads();
    if (threadIdx.x == 0) {
        float t = 0.f;
        #pragma unroll
        for (int i = 0; i < 8; i++) t += red[i];
        sinv = rsqrtf(t / cols + EPSF);
    }
    __syncthreads();
    const float inv = sinv;
    for (int c = threadIdx.x; c < cols; c += blockDim.x)
        d[c] = __float2half(s[c] * inv * w[c]);
}

// ---------------- k_rope precompute (half out) ----------------
__global__ void krope_k(const float* __restrict__ cqkv, const float* __restrict__ fc,
                        const float* __restrict__ fs, __half* __restrict__ kr)
{
    const int tok = blockIdx.x, i = threadIdx.x;   // 32 threads
    if (i >= RD / 2) return;
    const int t = tok & (SEQ - 1);
    const float* r = cqkv + (size_t)tok * (QLR + KVLR + RD) + QLR + KVLR;
    float a = r[2 * i], b = r[2 * i + 1];
    float c = fc[t * (RD / 2) + i], s = fs[t * (RD / 2) + i];
    kr[(size_t)tok * RD + 2 * i]     = __float2half(a * c - b * s);
    kr[(size_t)tok * RD + 2 * i + 1] = __float2half(a * s + b * c);
}

// ---------------- Q epilogue: QNR float -> Q half [tok,h,192] ----------------
__global__ void q_epi_k(const float* __restrict__ qnr, const float* __restrict__ qhw,
                        const float* __restrict__ fc, const float* __restrict__ fs,
                        __half* __restrict__ qout)
{
    const int tok = blockIdx.x, h = blockIdx.y, tid = threadIdx.x;  // 128 threads
    const int t = tok & (SEQ - 1);
    const float* src = qnr + (size_t)tok * (HEADS * ND + HEADS * RD) + (size_t)h * ND;
    float v = src[tid];
    float ss = warpSum(v * v);
    __shared__ float red[4];
    __shared__ float sinv;
    if ((tid & 31) == 0) red[tid >> 5] = ss;
    __syncthreads();
    if (tid == 0) sinv = rsqrtf((red[0] + red[1] + red[2] + red[3]) / ND + EPSF);
    __syncthreads();
    __half* dst = qout + ((size_t)tok * HEADS + h) * DQK;
    dst[tid] = __float2half(v * sinv * qhw[tid]);
    if (tid < RD / 2) {
        const float* r = qnr + (size_t)tok * (HEADS * ND + HEADS * RD)
                       + (size_t)HEADS * ND + (size_t)h * RD;
        float a = r[2 * tid], b = r[2 * tid + 1];
        float c = fc[t * (RD / 2) + tid], s = fs[t * (RD / 2) + tid];
        dst[ND + 2 * tid]     = __float2half(a * c - b * s);
        dst[ND + 2 * tid + 1] = __float2half(a * s + b * c);
    }
}

// ---------------- KV epilogue: KS half [b,h,s,192], V^T half [b,h,128,s] ----------------
__global__ void kv_epi_k(const float* __restrict__ kvup, const float* __restrict__ khw,
                         const __half* __restrict__ kr,
                         __half* __restrict__ ks, __half* __restrict__ vt)
{
    const int tok = blockIdx.x, h = blockIdx.y, tid = threadIdx.x;  // 128 threads
    const int b = tok >> 11;
    const int t = tok & (SEQ - 1);
    const float* src = kvup + ((size_t)tok * HEADS + h) * (ND + VD);
    float v = src[tid];
    float ss = warpSum(v * v);
    __shared__ float red[4];
    __shared__ float sinv;
    if ((tid & 31) == 0) red[tid >> 5] = ss;
    __syncthreads();
    if (tid == 0) sinv = rsqrtf((red[0] + red[1] + red[2] + red[3]) / ND + EPSF);
    __syncthreads();
    __half* ksb = ks + ((size_t)(b * HEADS + h) * SEQ + t) * DQK;
    ksb[tid] = __float2half(v * sinv * khw[tid]);
    vt[((size_t)(b * HEADS + h) * VD + tid) * SEQ + t] = __float2half(src[ND + tid]);
    if (tid < RD)
        ksb[ND + tid] = kr[(size_t)tok * RD + tid];   // already half
}

// ---------------- scale + causal softmax: SCORES float -> P half ----------------
__global__ void softmax_k(const float* __restrict__ scores, __half* __restrict__ P,
                          float scale)
{
    const int t = blockIdx.x;
    const int z = blockIdx.y;
    const float* row = scores + ((size_t)z * SEQ + t) * SEQ;
    __half* prow = P + ((size_t)z * SEQ + t) * SEQ;
    __shared__ float buf[SEQ];
    __shared__ float red[8];
    __shared__ float sstat;
    const int len = t + 1;

    float mx = -1e30f;
    for (int s = threadIdx.x; s < len; s += blockDim.x) {
        float v = row[s] * scale;
        buf[s] = v;
        mx = fmaxf(mx, v);
    }
    mx = warpMax(mx);
    if ((threadIdx.x & 31) == 0) red[threadIdx.x >> 5] = mx;
    __syncthreads();
    if (threadIdx.x == 0) {
        float m = -1e30f;
        #pragma unroll
        for (int i = 0; i < 8; i++) m = fmaxf(m, red[i]);
        sstat = m;
    }
    __syncthreads();
    mx = sstat;

    float sum = 0.f;
    for (int s = threadIdx.x; s < len; s += blockDim.x) {
        float e = __expf(buf[s] - mx);
        buf[s] = e;
        sum += e;
    }
    sum = warpSum(sum);
    __syncthreads();
    if ((threadIdx.x & 31) == 0) red[threadIdx.x >> 5] = sum;
    __syncthreads();
    if (threadIdx.x == 0) {
        float tt = 0.f;
        #pragma unroll
        for (int i = 0; i < 8; i++) tt += red[i];
        sstat = 1.f / tt;
    }
    __syncthreads();
    const float inv = sstat;
    for (int s = threadIdx.x; s < len; s += blockDim.x)
        prow[s] = __float2half(buf[s] * inv);
    const int zend = min(SEQ, (len + 127) & ~127);   // P@V reads to 128 boundary
    for (int s = len + threadIdx.x; s < zend; s += blockDim.x)
        prow[s] = __float2half(0.f);
}

// ---------------- Host driver ----------------
static inline void launch_gemm(const __half* A, const __half* B, void* C,
                               int M, int N, int K, int lda, int ldb, int ldc,
                               long long aB, long long aH, long long bB, long long bH,
                               long long cB, long long cH, int Hdim, int Z, int mode,
                               int halfC)
{
    dim3 grid((N + GBN - 1) / GBN, (M + GBM - 1) / GBM, Z);
    h16gemm_k<<<grid, 256, SMEM_GEMM_BYTES>>>(A, B, C, M, N, K, lda, ldb, ldc,
                                              aB, aH, bB, bH, cB, cH, Hdim, mode, halfC);
}

static inline void launch_transpose(const float* src, __half* dst, int R, int C)
{
    dim3 grid((C + 31) / 32, (R + 31) / 32);
    transpose_h_k<<<grid, dim3(32, 8)>>>(src, dst, R, C);
}

extern "C" void kernel_launch(void* const* d_in, const int* in_sizes, int n_in,
                              void* d_out, int out_size)
{
    const float* x        = (const float*)d_in[0];
    const float* fc       = (const float*)d_in[1];
    const float* fs       = (const float*)d_in[2];
    const float* q_down   = (const float*)d_in[3];
    const float* q_norm   = (const float*)d_in[4];
    const float* q_up_n   = (const float*)d_in[5];
    const float* q_up_r   = (const float*)d_in[6];
    const float* kv_down  = (const float*)d_in[7];
    const float* kv_norm  = (const float*)d_in[8];
    const float* kv_up    = (const float*)d_in[9];
    const float* qhw      = (const float*)d_in[10];
    const float* khw      = (const float*)d_in[11];
    const float* wo       = (const float*)d_in[12];
    float* out            = (float*)d_out;

    static bool attr_set = false;
    if (!attr_set) {
        cudaFuncSetAttribute(h16gemm_k, cudaFuncAttributeMaxDynamicSharedMemorySize,
                             SMEM_GEMM_BYTES);
        attr_set = true;
    }

    float* F = nullptr;
    __half* H = nullptr;
    cudaGetSymbolAddress((void**)&F, g_scratch);
    cudaGetSymbolAddress((void**)&H, g_hscr);

    float* CQKV   = F + F_CQKV;
    float* QNR    = F + F_QNR;
    float* KVUP   = F + F_KVUP;
    float* SCORES = F + F_SCORES;

    __half* XR    = H + H_XR;
    __half* W14   = H + H_W14;
    __half* W23   = H + H_W23;
    __half* W5    = H + H_W5;
    __half* W6    = H + H_W6;
    __half* CQ    = H + H_CQ;
    __half* CKV   = H + H_CKV;
    __half* Q     = H + H_Q;
    __half* KS    = H + H_KS;
    __half* VT    = H + H_VT;
    __half* KROPE = H + H_KROPE;
    __half* P     = H + H_P;
    __half* ATTN  = H + H_ATTN;

    const int NW14 = QLR + KVLR + RD;          // 2112
    const int NW23 = HEADS * ND + HEADS * RD;  // 3072

    // 0) convert/transposes needed for GEMM1 only (5 launches) so the big
    //    merged GEMM1 is launch #6 — ncu -s 5 -c 1 captures it.
    {
        size_t n = (size_t)NTOK * DIM;
        halfcopy_k<<<(int)((n + 1023) / 1024), 256>>>(x, XR, (int)n);       // 1
    }
    launch_transpose(q_down,  W14,                      DIM,  QLR);          // 2
    launch_transpose(kv_down, W14 + (size_t)QLR * DIM,  DIM,  KVLR + RD);    // 3
    launch_transpose(q_up_n,  W23,                      QLR,  HEADS * ND);   // 4
    launch_transpose(q_up_r,  W23 + (size_t)HEADS * ND * QLR, QLR, HEADS * RD); // 5

    // 1) [c_q | kv_raw] = x @ [q_down | kv_down]   (merged)   -- launch 6
    launch_gemm(XR, W14, CQKV, NTOK, NW14, DIM, DIM, DIM, NW14,
                0, 0, 0, 0, 0, 0, 1, 1, 0, 0);

    // remaining weight transposes (independent of GEMM1 result)
    launch_transpose(kv_up,   W5,  KVLR, HEADS * (ND + VD));
    launch_transpose(wo,      W6,  HEADS * VD, DIM);

    rmsnorm_k<<<NTOK, 256>>>(CQKV,        CQ,  q_norm,  QLR,  NW14, QLR);
    rmsnorm_k<<<NTOK, 256>>>(CQKV + QLR,  CKV, kv_norm, KVLR, NW14, KVLR);
    krope_k<<<NTOK, 32>>>(CQKV, fc, fs, KROPE);

    // 2) [q_nope | q_rope] = c_q @ [q_up_n | q_up_r]   (merged) + epilogue
    launch_gemm(CQ, W23, QNR, NTOK, NW23, QLR, QLR, QLR, NW23,
                0, 0, 0, 0, 0, 0, 1, 1, 0, 0);
    q_epi_k<<<dim3(NTOK, HEADS), 128>>>(QNR, qhw, fc, fs, Q);

    // 3) kv up-projection + epilogue -> KS, VT
    launch_gemm(CKV, W5, KVUP, NTOK, HEADS * (ND + VD), KVLR,
                KVLR, KVLR, HEADS * (ND + VD),
                0, 0, 0, 0, 0, 0, 1, 1, 0, 0);
    kv_epi_k<<<dim3(NTOK, HEADS), 128>>>(KVUP, khw, KROPE, KS, VT);

    // 4) scores = Q @ K^T per (b,h)  [causal tiles skipped]
    launch_gemm(Q, KS, SCORES, SEQ, SEQ, DQK,
                HEADS * DQK, DQK, SEQ,
                (long long)SEQ * HEADS * DQK, DQK,
                (long long)HEADS * SEQ * DQK, (long long)SEQ * DQK,
                (long long)HEADS * SEQ * SEQ, (long long)SEQ * SEQ,
                HEADS, BATCH * HEADS, 1, 0);

    // 5) scale + causal softmax -> P (half)
    {
        float scale = 1.0f / sqrtf((float)DQK);
        softmax_k<<<dim3(SEQ, BATCH * HEADS), 256>>>(SCORES, P, scale);
    }

    // 6) attn_out = P @ V per (b,h)  [K-trunc; direct half output]
    launch_gemm(P, VT, ATTN, SEQ, VD, SEQ,
                SEQ, SEQ, HEADS * VD,
                (long long)HEADS * SEQ * SEQ, (long long)SEQ * SEQ,
                (long long)HEADS * VD * SEQ, (long long)VD * SEQ,
                (long long)SEQ * HEADS * VD, VD,
                HEADS, BATCH * HEADS, 2, 1);

    // 7) out = attn_out @ wo_w
    launch_gemm(ATTN, W6, out, NTOK, DIM, HEADS * VD,
                HEADS * VD, HEADS * VD, DIM,
                0, 0, 0, 0, 0, 0, 1, 1, 0, 0);
}